// round 4
// baseline (speedup 1.0000x reference)
#include <cuda_runtime.h>
#include <cuda_bf16.h>
#include <math.h>
#include <stdint.h>

#define R_DIM 128
#define C_DIM 256
#define E_DIM 768
#define H_DIM 12
#define DK_DIM 64
#define MROWS (R_DIM * C_DIM)            // 32768
#define PHEAD (R_DIM * DK_DIM)           // 8192
#define SPLIT_S 16
#define SCORES_ELEMS (H_DIM * C_DIM * C_DIM)   // 786432
#define OUT_ELEMS ((size_t)MROWS * E_DIM)      // 25165824
#define W_ELEMS (E_DIM * E_DIM)                // 589824

typedef unsigned short u16;

// ---------------- scratch (device globals; allocation-free rule) ----------------
__device__ u16 g_xh[OUT_ELEMS],  g_xl[OUT_ELEMS];
__device__ u16 g_wqh[W_ELEMS], g_wql[W_ELEMS];
__device__ u16 g_wkh[W_ELEMS], g_wkl[W_ELEMS];
__device__ u16 g_wvh[W_ELEMS], g_wvl[W_ELEMS];
__device__ u16 g_woh[W_ELEMS], g_wol[W_ELEMS];
__device__ u16 g_qth[OUT_ELEMS], g_qtl[OUT_ELEMS];   // [h][i][r*64+d]
__device__ u16 g_kth[OUT_ELEMS], g_ktl[OUT_ELEMS];   // [h][j][r*64+d]
__device__ u16 g_vth[OUT_ELEMS], g_vtl[OUT_ELEMS];   // [h][r*64+d][j]
__device__ u16 g_pbh[SCORES_ELEMS], g_pbl[SCORES_ELEMS]; // probs bf16 [h][i][j]
__device__ u16 g_cbh[OUT_ELEMS], g_cbl[OUT_ELEMS];   // [(r*C+i)][h*64+d]
__device__ float g_part[(size_t)SPLIT_S * SCORES_ELEMS]; // scores split-K partials
__device__ float g_probs[SCORES_ELEMS];

// ---------------- helpers ----------------
__device__ __forceinline__ uint32_t smem_u32(const void* p) {
    uint32_t a;
    asm("{ .reg .u64 t; cvta.to.shared.u64 t, %1; cvt.u32.u64 %0, t; }" : "=r"(a) : "l"(p));
    return a;
}

// fp32 pair -> (hi pair via truncation, lo pair rounded). low bf16 = x, high = y.
__device__ __forceinline__ void split2(float x, float y, uint32_t& h, uint32_t& l) {
    uint32_t ux = __float_as_uint(x), uy = __float_as_uint(y);
    asm("prmt.b32 %0, %1, %2, 0x7632;" : "=r"(h) : "r"(ux), "r"(uy));
    float hx = __uint_as_float(ux & 0xffff0000u);
    float hy = __uint_as_float(uy & 0xffff0000u);
    asm("cvt.rn.bf16x2.f32 %0, %1, %2;" : "=r"(l) : "f"(y - hy), "f"(x - hx));
}
__device__ __forceinline__ void split1(float x, u16& h, u16& l) {
    uint32_t ux = __float_as_uint(x);
    h = (u16)(ux >> 16);
    float hx = __uint_as_float(ux & 0xffff0000u);
    __nv_bfloat16 lb = __float2bfloat16(x - hx);
    l = *reinterpret_cast<u16*>(&lb);
}

__device__ __forceinline__ void ldm4(uint32_t r[4], uint32_t addr) {
    asm volatile("ldmatrix.sync.aligned.m8n8.x4.shared.b16 {%0,%1,%2,%3}, [%4];"
                 : "=r"(r[0]), "=r"(r[1]), "=r"(r[2]), "=r"(r[3]) : "r"(addr));
}
__device__ __forceinline__ void mma_bf16(float c[4], const uint32_t a[4],
                                         uint32_t b0, uint32_t b1) {
    asm volatile("mma.sync.aligned.m16n8k16.row.col.f32.bf16.bf16.f32 "
        "{%0,%1,%2,%3}, {%4,%5,%6,%7}, {%8,%9}, {%0,%1,%2,%3};"
        : "+f"(c[0]), "+f"(c[1]), "+f"(c[2]), "+f"(c[3])
        : "r"(a[0]), "r"(a[1]), "r"(a[2]), "r"(a[3]), "r"(b0), "r"(b1));
}
#define CP16(dst, src) \
    asm volatile("cp.async.cg.shared.global [%0], [%1], 16;" :: "r"(dst), "l"(src) : "memory")
#define CP_COMMIT() asm volatile("cp.async.commit_group;" ::: "memory")
#define CP_WAITN(n) asm volatile("cp.async.wait_group %0;" :: "n"(n) : "memory")

// ---------------- input convert kernel: fp32 -> bf16 hi/lo ----------------
__global__ __launch_bounds__(256)
void convert_split(const float* __restrict__ src, u16* __restrict__ h,
                   u16* __restrict__ l, int n4)
{
    for (int i = blockIdx.x * blockDim.x + threadIdx.x; i < n4; i += gridDim.x * blockDim.x) {
        float4 v = reinterpret_cast<const float4*>(src)[i];
        uint32_t h01, l01, h23, l23;
        split2(v.x, v.y, h01, l01);
        split2(v.z, v.w, h23, l23);
        reinterpret_cast<uint2*>(h)[i] = make_uint2(h01, h23);
        reinterpret_cast<uint2*>(l)[i] = make_uint2(l01, l23);
    }
}

// ---------------- HMMA GEMM: C = A(MxK) * B(NxK)^T, bf16 hi/lo 3-product ----------------
// Tile: 128(M) x 256(N) x 32(K), 512 threads (16 warps, warp tile 32x64), 3-stage cp.async.
enum { M_PLAIN = 0, M_QK = 1, M_V = 2, M_SCORES = 3, M_AV = 4 };

// stage: Ah 10240 | Al 10240 | Bh 20480 | Bl 20480 = 61440 B
#define STAGE_B 61440
#define NSTAGE  3
#define DYN_B   (NSTAGE * STAGE_B)       // 184320; epilogue fsm 128*260*4=133120 fits

template<int MODE>
__global__ __launch_bounds__(512, 1)
void hm_gemm(const u16* __restrict__ Ah, const u16* __restrict__ Al,
             const u16* __restrict__ Bh, const u16* __restrict__ Bl,
             const float* __restrict__ bias, float* __restrict__ outF,
             u16* __restrict__ outH, u16* __restrict__ outL,
             int K, int lda, int ldb, float alpha)
{
    extern __shared__ char dynsmem[];
    const int t    = threadIdx.x;
    const int lane = t & 31;
    const int wid  = t >> 5;          // 0..15
    const int wm   = (wid & 3) * 32;  // 0..96
    const int wn   = (wid >> 2) * 64; // 0..192
    const int m0   = blockIdx.y * 128;
    const int n0   = blockIdx.x * 256;

    int hz = 0;
    if (MODE == M_SCORES) {
        const int z = blockIdx.z;
        const int h = z >> 4, s = z & 15;
        const size_t off = (size_t)h * C_DIM * PHEAD + (size_t)s * (PHEAD / SPLIT_S);
        Ah += off; Al += off; Bh += off; Bl += off;
        outF += (size_t)z * (C_DIM * C_DIM);
    } else if (MODE == M_AV) {
        hz = blockIdx.z;
        const size_t ao = (size_t)hz * C_DIM * C_DIM;
        const size_t bo = (size_t)hz * PHEAD * C_DIM;
        Ah += ao; Al += ao; Bh += bo; Bl += bo;
    }

    const uint32_t smb = smem_u32(dynsmem);
    const int NC = K >> 5;

    // -------- cp.async issue of one 32-K chunk into stage s --------
    auto issue = [&](int c, int s) {
        const int kk = c << 5;
        const uint32_t sb = smb + s * STAGE_B;
        {   // A: 128 rows * 4 seg = 512 ops -> 1 per thread (hi + lo)
            const int row = t >> 2;
            const int k8  = t & 3;
            const uint32_t so = (uint32_t)(row * 80 + k8 * 16);
            const size_t ga = (size_t)(m0 + row) * lda + kk + k8 * 8;
            CP16(sb +     0 + so, Ah + ga);
            CP16(sb + 10240 + so, Al + ga);
        }
#pragma unroll
        for (int it = 0; it < 2; it++) {   // B: 256 rows * 4 seg = 1024 ops -> 2 per thread
            const int f   = t + it * 512;
            const int row = f >> 2;
            const int k8  = f & 3;
            const uint32_t so = (uint32_t)(row * 80 + k8 * 16);
            const size_t gb = (size_t)(n0 + row) * ldb + kk + k8 * 8;
            CP16(sb + 20480 + so, Bh + gb);
            CP16(sb + 40960 + so, Bl + gb);
        }
        CP_COMMIT();
    };

    float acc[2][8][4];
#pragma unroll
    for (int mt = 0; mt < 2; mt++)
#pragma unroll
        for (int nt = 0; nt < 8; nt++)
#pragma unroll
            for (int e = 0; e < 4; e++) acc[mt][nt][e] = 0.0f;

    const uint32_t ro = (uint32_t)(((lane >> 3) & 1) * 8 + (lane & 7));
    const uint32_t co = (lane & 16) ? 16u : 0u;
    const uint32_t aoff = (uint32_t)(wm + ro) * 80 + co;
    const uint32_t boff = (uint32_t)(wn + ro) * 80 + co;

    issue(0, 0);
    if (NC > 1) issue(1, 1);
    if (NC > 2) issue(2, 2);

    for (int c = 0; c < NC; c++) {
        if (c + 1 >= NC)      { CP_WAITN(0); }
        else if (c + 2 >= NC) { CP_WAITN(1); }
        else                  { CP_WAITN(2); }
        __syncthreads();

        const uint32_t sb = smb + (c % 3) * STAGE_B;
#pragma unroll
        for (int kh = 0; kh < 2; kh++) {
            const uint32_t kB = kh * 32;
            uint32_t aH[2][4], aL[2][4], bH[4][4];
            ldm4(aH[0], sb + aoff + kB);
            ldm4(aH[1], sb + aoff + 16 * 80 + kB);
#pragma unroll
            for (int np = 0; np < 4; np++)
                ldm4(bH[np], sb + 20480 + boff + np * 16 * 80 + kB);
            // pass 1: Ah * Bh
#pragma unroll
            for (int mt = 0; mt < 2; mt++)
#pragma unroll
                for (int np = 0; np < 4; np++) {
                    mma_bf16(acc[mt][np * 2 + 0], aH[mt], bH[np][0], bH[np][2]);
                    mma_bf16(acc[mt][np * 2 + 1], aH[mt], bH[np][1], bH[np][3]);
                }
            // pass 2: Al * Bh
            ldm4(aL[0], sb + 10240 + aoff + kB);
            ldm4(aL[1], sb + 10240 + aoff + 16 * 80 + kB);
#pragma unroll
            for (int mt = 0; mt < 2; mt++)
#pragma unroll
                for (int np = 0; np < 4; np++) {
                    mma_bf16(acc[mt][np * 2 + 0], aL[mt], bH[np][0], bH[np][2]);
                    mma_bf16(acc[mt][np * 2 + 1], aL[mt], bH[np][1], bH[np][3]);
                }
            // pass 3: Ah * Bl
#pragma unroll
            for (int np = 0; np < 4; np++) {
                uint32_t bL[4];
                ldm4(bL, sb + 40960 + boff + np * 16 * 80 + kB);
                mma_bf16(acc[0][np * 2 + 0], aH[0], bL[0], bL[2]);
                mma_bf16(acc[0][np * 2 + 1], aH[0], bL[1], bL[3]);
                mma_bf16(acc[1][np * 2 + 0], aH[1], bL[0], bL[2]);
                mma_bf16(acc[1][np * 2 + 1], aH[1], bL[1], bL[3]);
            }
        }
        __syncthreads();
        if (c + 3 < NC) issue(c + 3, (c + 3) % 3);
    }

    // -------- epilogue: acc -> smem fp32 staging (128x260) -> global --------
    float* fsm = reinterpret_cast<float*>(dynsmem);
    {
        const int g  = lane >> 2;
        const int tg = lane & 3;
#pragma unroll
        for (int mt = 0; mt < 2; mt++)
#pragma unroll
            for (int nt = 0; nt < 8; nt++) {
                const int r0 = wm + mt * 16 + g;
                const int cc = wn + nt * 8 + 2 * tg;
                *reinterpret_cast<float2*>(&fsm[r0 * 260 + cc]) =
                    make_float2(acc[mt][nt][0], acc[mt][nt][1]);
                *reinterpret_cast<float2*>(&fsm[(r0 + 8) * 260 + cc]) =
                    make_float2(acc[mt][nt][2], acc[mt][nt][3]);
            }
    }
    __syncthreads();

    if (MODE == M_V) {
        // transposed scatter: vt[h][r*64+d][j] (+ bias), coalesced along j
#pragma unroll 8
        for (int i = 0; i < 64; i++) {
            const int f = t + i * 512;      // 0..32767
            const int m = f & 127;          // tile row  -> (r, j)
            const int n = f >> 7;           // tile col  -> (h, d)
            const int ng = n0 + n;
            float v = fsm[m * 260 + n] + bias[ng];
            const int h = ng >> 6, d = ng & 63;
            const int mg = m0 + m;
            const int r = mg >> 8, j = mg & 255;
            u16 hh, ll;
            split1(v, hh, ll);
            const size_t oi = ((size_t)h * PHEAD + r * 64 + d) * C_DIM + j;
            outH[oi] = hh; outL[oi] = ll;
        }
    } else {
#pragma unroll
        for (int i = 0; i < 16; i++) {
            const int f = t + i * 512;      // 0..8191 float4 units
            const int row = f >> 6;         // 64 float4 per row
            const int q   = f & 63;
            float4 v = *reinterpret_cast<const float4*>(&fsm[row * 260 + q * 4]);
            const int m = m0 + row;
            const int n = n0 + q * 4;
            if (MODE == M_SCORES) {
                *reinterpret_cast<float4*>(&outF[(size_t)m * C_DIM + n]) = v;
            } else if (MODE == M_PLAIN) {
                float4 bb = *reinterpret_cast<const float4*>(&bias[n]);
                v.x += bb.x; v.y += bb.y; v.z += bb.z; v.w += bb.w;
                *reinterpret_cast<float4*>(&outF[(size_t)m * E_DIM + n]) = v;
            } else if (MODE == M_QK) {
                float4 bb = *reinterpret_cast<const float4*>(&bias[n]);
                v.x = (v.x + bb.x) * alpha; v.y = (v.y + bb.y) * alpha;
                v.z = (v.z + bb.z) * alpha; v.w = (v.w + bb.w) * alpha;
                uint32_t h01, l01, h23, l23;
                split2(v.x, v.y, h01, l01);
                split2(v.z, v.w, h23, l23);
                const int h = n >> 6, d = n & 63;
                const int r = m >> 8, ij = m & 255;
                const size_t oi = ((size_t)h * C_DIM + ij) * PHEAD + r * 64 + d;
                *reinterpret_cast<uint2*>(&outH[oi]) = make_uint2(h01, h23);
                *reinterpret_cast<uint2*>(&outL[oi]) = make_uint2(l01, l23);
            } else { // M_AV -> cb[(r*C+i)][hz*64+d]
                uint32_t h01, l01, h23, l23;
                split2(v.x, v.y, h01, l01);
                split2(v.z, v.w, h23, l23);
                const int r = n >> 6, d = n & 63;
                const size_t oi = ((size_t)r * C_DIM + m) * E_DIM + hz * 64 + d;
                *reinterpret_cast<uint2*>(&outH[oi]) = make_uint2(h01, h23);
                *reinterpret_cast<uint2*>(&outL[oi]) = make_uint2(l01, l23);
            }
        }
    }
}

// ---------------- softmax: reduce split-K partials, softmax, emit fp32 + bf16 ----------------
__global__ __launch_bounds__(256)
void softmax_kernel(const float* __restrict__ part, float* __restrict__ probs,
                    float* __restrict__ probs_out,
                    u16* __restrict__ pbh, u16* __restrict__ pbl)
{
    const int row = blockIdx.x;          // h*256 + i
    const int h = row >> 8;
    const int i = row & 255;
    const int j = threadIdx.x;

    float v = 0.0f;
#pragma unroll
    for (int s = 0; s < SPLIT_S; s++)
        v += part[((size_t)(h * SPLIT_S + s)) * (C_DIM * C_DIM) + (size_t)i * C_DIM + j];

    __shared__ float red[256];
    red[j] = v;
    __syncthreads();
#pragma unroll
    for (int off = 128; off > 0; off >>= 1) {
        if (j < off) red[j] = fmaxf(red[j], red[j + off]);
        __syncthreads();
    }
    const float mx = red[0];
    __syncthreads();
    const float e = expf(v - mx);
    red[j] = e;
    __syncthreads();
#pragma unroll
    for (int off = 128; off > 0; off >>= 1) {
        if (j < off) red[j] += red[j + off];
        __syncthreads();
    }
    const float p = e / red[0];

    const size_t idx = (size_t)row * C_DIM + j;
    probs[idx] = p;
    if (probs_out) probs_out[idx] = p;
    u16 hh, ll;
    split1(p, hh, ll);
    pbh[idx] = hh; pbl[idx] = ll;
}

// ---------------- launch ----------------
extern "C" void kernel_launch(void* const* d_in, const int* in_sizes, int n_in,
                              void* d_out, int out_size)
{
    const float* x  = (const float*)d_in[0];
    const float* Wq = (const float*)d_in[1];
    const float* bq = (const float*)d_in[2];
    const float* Wk = (const float*)d_in[3];
    const float* bk = (const float*)d_in[4];
    const float* Wv = (const float*)d_in[5];
    const float* bv = (const float*)d_in[6];
    const float* Wo = (const float*)d_in[7];
    const float* bo = (const float*)d_in[8];
    float* out = (float*)d_out;

    float* probs_out = nullptr;
    if ((size_t)out_size >= OUT_ELEMS + SCORES_ELEMS)
        probs_out = out + ((size_t)out_size - SCORES_ELEMS);

    u16 *xh, *xl, *wqh, *wql, *wkh, *wkl, *wvh, *wvl, *woh, *wol;
    u16 *qth, *qtl, *kth, *ktl, *vth, *vtl, *pbh, *pbl, *cbh, *cbl;
    float *part, *probs;
    cudaGetSymbolAddress((void**)&xh, g_xh);   cudaGetSymbolAddress((void**)&xl, g_xl);
    cudaGetSymbolAddress((void**)&wqh, g_wqh); cudaGetSymbolAddress((void**)&wql, g_wql);
    cudaGetSymbolAddress((void**)&wkh, g_wkh); cudaGetSymbolAddress((void**)&wkl, g_wkl);
    cudaGetSymbolAddress((void**)&wvh, g_wvh); cudaGetSymbolAddress((void**)&wvl, g_wvl);
    cudaGetSymbolAddress((void**)&woh, g_woh); cudaGetSymbolAddress((void**)&wol, g_wol);
    cudaGetSymbolAddress((void**)&qth, g_qth); cudaGetSymbolAddress((void**)&qtl, g_qtl);
    cudaGetSymbolAddress((void**)&kth, g_kth); cudaGetSymbolAddress((void**)&ktl, g_ktl);
    cudaGetSymbolAddress((void**)&vth, g_vth); cudaGetSymbolAddress((void**)&vtl, g_vtl);
    cudaGetSymbolAddress((void**)&pbh, g_pbh); cudaGetSymbolAddress((void**)&pbl, g_pbl);
    cudaGetSymbolAddress((void**)&cbh, g_cbh); cudaGetSymbolAddress((void**)&cbl, g_cbl);
    cudaGetSymbolAddress((void**)&part, g_part);
    cudaGetSymbolAddress((void**)&probs, g_probs);

    cudaFuncSetAttribute(hm_gemm<M_PLAIN>,  cudaFuncAttributeMaxDynamicSharedMemorySize, DYN_B);
    cudaFuncSetAttribute(hm_gemm<M_QK>,     cudaFuncAttributeMaxDynamicSharedMemorySize, DYN_B);
    cudaFuncSetAttribute(hm_gemm<M_V>,      cudaFuncAttributeMaxDynamicSharedMemorySize, DYN_B);
    cudaFuncSetAttribute(hm_gemm<M_SCORES>, cudaFuncAttributeMaxDynamicSharedMemorySize, DYN_B);
    cudaFuncSetAttribute(hm_gemm<M_AV>,     cudaFuncAttributeMaxDynamicSharedMemorySize, DYN_B);

    const float scaling = (float)(1.0 / (8.0 * sqrt(128.0)));

    // input conversions
    convert_split<<<1024, 256>>>(x,  xh,  xl,  OUT_ELEMS / 4);
    convert_split<<<288,  256>>>(Wq, wqh, wql, W_ELEMS / 4);
    convert_split<<<288,  256>>>(Wk, wkh, wkl, W_ELEMS / 4);
    convert_split<<<288,  256>>>(Wv, wvh, wvl, W_ELEMS / 4);
    convert_split<<<288,  256>>>(Wo, woh, wol, W_ELEMS / 4);

    dim3 blk(512);
    dim3 gproj(E_DIM / 256, MROWS / 128, 1);            // (3, 256)

    hm_gemm<M_QK><<<gproj, blk, DYN_B>>>(xh, xl, wqh, wql, bq, nullptr, qth, qtl,
                                         E_DIM, E_DIM, E_DIM, scaling);
    hm_gemm<M_QK><<<gproj, blk, DYN_B>>>(xh, xl, wkh, wkl, bk, nullptr, kth, ktl,
                                         E_DIM, E_DIM, E_DIM, 1.0f);
    hm_gemm<M_V><<<gproj, blk, DYN_B>>>(xh, xl, wvh, wvl, bv, nullptr, vth, vtl,
                                        E_DIM, E_DIM, E_DIM, 1.0f);

    dim3 gsc(C_DIM / 256, C_DIM / 128, H_DIM * SPLIT_S); // (1, 2, 192)
    hm_gemm<M_SCORES><<<gsc, blk, DYN_B>>>(qth, qtl, kth, ktl, nullptr, part,
                                           nullptr, nullptr,
                                           PHEAD / SPLIT_S, PHEAD, PHEAD, 1.0f);

    softmax_kernel<<<H_DIM * C_DIM, 256>>>(part, probs, probs_out, pbh, pbl);

    dim3 gav(PHEAD / 256, C_DIM / 128, H_DIM);           // (32, 2, 12)
    hm_gemm<M_AV><<<gav, blk, DYN_B>>>(pbh, pbl, vth, vtl, nullptr, nullptr,
                                       cbh, cbl, C_DIM, C_DIM, C_DIM, 1.0f);

    hm_gemm<M_PLAIN><<<gproj, blk, DYN_B>>>(cbh, cbl, woh, wol, bo, out,
                                            nullptr, nullptr, E_DIM, E_DIM, E_DIM, 1.0f);
}

// round 5
// speedup vs baseline: 1.4553x; 1.4553x over previous
#include <cuda_runtime.h>
#include <cuda_bf16.h>
#include <cuda_fp16.h>
#include <math.h>
#include <stdint.h>

#define R_DIM 128
#define C_DIM 256
#define E_DIM 768
#define H_DIM 12
#define DK_DIM 64
#define MROWS (R_DIM * C_DIM)            // 32768
#define PHEAD (R_DIM * DK_DIM)           // 8192
#define SPLIT_S 16
#define SCORES_ELEMS (H_DIM * C_DIM * C_DIM)   // 786432
#define OUT_ELEMS ((size_t)MROWS * E_DIM)      // 25165824
#define W_ELEMS (E_DIM * E_DIM)                // 589824

typedef unsigned short u16;

// ---------------- scratch ----------------
__device__ u16 g_xh[OUT_ELEMS],  g_xl[OUT_ELEMS];        // fp16 hi/lo
__device__ u16 g_wqh[W_ELEMS], g_wql[W_ELEMS];           // fp16
__device__ u16 g_wkh[W_ELEMS], g_wkl[W_ELEMS];
__device__ u16 g_wvh[W_ELEMS], g_wvl[W_ELEMS];
__device__ u16 g_woh[W_ELEMS], g_wol[W_ELEMS];
__device__ u16 g_qth[OUT_ELEMS], g_qtl[OUT_ELEMS];       // bf16 [h][i][r*64+d]
__device__ u16 g_kth[OUT_ELEMS], g_ktl[OUT_ELEMS];       // bf16 [h][j][r*64+d]
__device__ u16 g_vth[OUT_ELEMS], g_vtl[OUT_ELEMS];       // bf16 [h][r*64+d][j]
__device__ u16 g_pbh[SCORES_ELEMS], g_pbl[SCORES_ELEMS]; // bf16 probs [h][i][j]
__device__ u16 g_cbh[OUT_ELEMS], g_cbl[OUT_ELEMS];       // fp16 [(r*C+i)][h*64+d]
__device__ float g_part[(size_t)SPLIT_S * SCORES_ELEMS];
__device__ float g_probs[SCORES_ELEMS];

// ---------------- helpers ----------------
__device__ __forceinline__ uint32_t smem_u32(const void* p) {
    uint32_t a;
    asm("{ .reg .u64 t; cvta.to.shared.u64 t, %1; cvt.u32.u64 %0, t; }" : "=r"(a) : "l"(p));
    return a;
}

// bf16 split: hi = truncation, lo = RN residual; low 16 bits = x
__device__ __forceinline__ void split2(float x, float y, uint32_t& h, uint32_t& l) {
    uint32_t ux = __float_as_uint(x), uy = __float_as_uint(y);
    asm("prmt.b32 %0, %1, %2, 0x7632;" : "=r"(h) : "r"(ux), "r"(uy));
    float hx = __uint_as_float(ux & 0xffff0000u);
    float hy = __uint_as_float(uy & 0xffff0000u);
    asm("cvt.rn.bf16x2.f32 %0, %1, %2;" : "=r"(l) : "f"(y - hy), "f"(x - hx));
}
__device__ __forceinline__ void split1(float x, u16& h, u16& l) {
    uint32_t ux = __float_as_uint(x);
    h = (u16)(ux >> 16);
    float hx = __uint_as_float(ux & 0xffff0000u);
    __nv_bfloat16 lb = __float2bfloat16(x - hx);
    l = *reinterpret_cast<u16*>(&lb);
}
// fp16 split: hi = RN(x), lo = RN(x - hi); low 16 bits = x
__device__ __forceinline__ void splitH2(float x, float y, uint32_t& h, uint32_t& l) {
    __half2 h2 = __floats2half2_rn(x, y);
    float2 hf = __half22float2(h2);
    __half2 l2 = __floats2half2_rn(x - hf.x, y - hf.y);
    h = *reinterpret_cast<uint32_t*>(&h2);
    l = *reinterpret_cast<uint32_t*>(&l2);
}

__device__ __forceinline__ void ldm4(uint32_t r[4], uint32_t addr) {
    asm volatile("ldmatrix.sync.aligned.m8n8.x4.shared.b16 {%0,%1,%2,%3}, [%4];"
                 : "=r"(r[0]), "=r"(r[1]), "=r"(r[2]), "=r"(r[3]) : "r"(addr));
}
__device__ __forceinline__ void mma_bf16(float c[4], const uint32_t a[4],
                                         uint32_t b0, uint32_t b1) {
    asm volatile("mma.sync.aligned.m16n8k16.row.col.f32.bf16.bf16.f32 "
        "{%0,%1,%2,%3}, {%4,%5,%6,%7}, {%8,%9}, {%0,%1,%2,%3};"
        : "+f"(c[0]), "+f"(c[1]), "+f"(c[2]), "+f"(c[3])
        : "r"(a[0]), "r"(a[1]), "r"(a[2]), "r"(a[3]), "r"(b0), "r"(b1));
}
__device__ __forceinline__ void mma_fp16(float c[4], const uint32_t a[4],
                                         uint32_t b0, uint32_t b1) {
    asm volatile("mma.sync.aligned.m16n8k16.row.col.f32.f16.f16.f32 "
        "{%0,%1,%2,%3}, {%4,%5,%6,%7}, {%8,%9}, {%0,%1,%2,%3};"
        : "+f"(c[0]), "+f"(c[1]), "+f"(c[2]), "+f"(c[3])
        : "r"(a[0]), "r"(a[1]), "r"(a[2]), "r"(a[3]), "r"(b0), "r"(b1));
}
#define CP16(dst, src) \
    asm volatile("cp.async.cg.shared.global [%0], [%1], 16;" :: "r"(dst), "l"(src) : "memory")
#define CP_COMMIT() asm volatile("cp.async.commit_group;" ::: "memory")
#define CP_WAITN(n) asm volatile("cp.async.wait_group %0;" :: "n"(n) : "memory")

// ---------------- input convert: fp32 -> fp16 hi/lo ----------------
__global__ __launch_bounds__(256)
void convert_splitH(const float* __restrict__ src, u16* __restrict__ h,
                    u16* __restrict__ l, int n4)
{
    for (int i = blockIdx.x * blockDim.x + threadIdx.x; i < n4; i += gridDim.x * blockDim.x) {
        float4 v = reinterpret_cast<const float4*>(src)[i];
        uint32_t h01, l01, h23, l23;
        splitH2(v.x, v.y, h01, l01);
        splitH2(v.z, v.w, h23, l23);
        reinterpret_cast<uint2*>(h)[i] = make_uint2(h01, h23);
        reinterpret_cast<uint2*>(l)[i] = make_uint2(l01, l23);
    }
}

// ---------------- HMMA GEMM: C = A(MxK) * B(NxK)^T ----------------
// NPASS=2: fp16 (AhBh + AlBh), 3-stage.  NPASS=3: bf16 (AhBh + AlBh + AhBl), 2-stage.
// Tile 128x128x32, 256 threads (8 warps, warp tile 32x64), 2 CTA/SM.
enum { M_PLAIN = 0, M_QK = 1, M_V = 2, M_SCORES = 3, M_AV = 4 };

template<int NPASS> struct Cfg;
template<> struct Cfg<2> { static const int STAGE = 30720, NST = 3, DYN = 92160; };
template<> struct Cfg<3> { static const int STAGE = 40960, NST = 2, DYN = 81920; };

template<int MODE, int NPASS>
__global__ __launch_bounds__(256, 2)
void hm_gemm(const u16* __restrict__ Ah, const u16* __restrict__ Al,
             const u16* __restrict__ Bh, const u16* __restrict__ Bl,
             const float* __restrict__ bias, float* __restrict__ outF,
             u16* __restrict__ outH, u16* __restrict__ outL,
             int K, int lda, int ldb, float alpha)
{
    extern __shared__ char dynsmem[];
    const int t    = threadIdx.x;
    const int lane = t & 31;
    const int wid  = t >> 5;
    const int wm   = (wid & 3) * 32;
    const int wn   = (wid >> 2) * 64;
    const int m0   = blockIdx.y * 128;
    const int n0   = blockIdx.x * 128;
    const int STAGE = Cfg<NPASS>::STAGE;
    const int NST   = Cfg<NPASS>::NST;

    int hz = 0;
    if (MODE == M_SCORES) {
        const int z = blockIdx.z;
        const int h = z >> 4, s = z & 15;
        const size_t off = (size_t)h * C_DIM * PHEAD + (size_t)s * (PHEAD / SPLIT_S);
        Ah += off; Al += off; Bh += off; Bl += off;
        outF += (size_t)z * (C_DIM * C_DIM);
    } else if (MODE == M_AV) {
        hz = blockIdx.z;
        const size_t ao = (size_t)hz * C_DIM * C_DIM;
        const size_t bo = (size_t)hz * PHEAD * C_DIM;
        Ah += ao; Al += ao; Bh += bo; Bl += bo;
    }

    const uint32_t smb = smem_u32(dynsmem);
    const int NC = K >> 5;

    auto issue = [&](int c, int s) {
        const int kk = c << 5;
        const uint32_t sb = smb + s * STAGE;
#pragma unroll
        for (int it = 0; it < 2; it++) {
            const int f   = t + it * 256;      // 0..511
            const int row = f >> 2;            // 0..127
            const int k8  = f & 3;
            const uint32_t so = (uint32_t)(row * 80 + k8 * 16);
            const size_t ga = (size_t)(m0 + row) * lda + kk + k8 * 8;
            const size_t gb = (size_t)(n0 + row) * ldb + kk + k8 * 8;
            CP16(sb +     0 + so, Ah + ga);
            CP16(sb + 10240 + so, Al + ga);
            CP16(sb + 20480 + so, Bh + gb);
            if (NPASS == 3) CP16(sb + 30720 + so, Bl + gb);
        }
        CP_COMMIT();
    };

    float acc[2][8][4];
#pragma unroll
    for (int mt = 0; mt < 2; mt++)
#pragma unroll
        for (int nt = 0; nt < 8; nt++)
#pragma unroll
            for (int e = 0; e < 4; e++) acc[mt][nt][e] = 0.0f;

    const uint32_t ro = (uint32_t)(((lane >> 3) & 1) * 8 + (lane & 7));
    const uint32_t co = (lane & 16) ? 16u : 0u;
    const uint32_t aoff = (uint32_t)(wm + ro) * 80 + co;
    const uint32_t boff = (uint32_t)(wn + ro) * 80 + co;

    issue(0, 0);
    if (NC > 1) issue(1, 1);
    if (NST == 3 && NC > 2) issue(2, 2);

    for (int c = 0; c < NC; c++) {
        if (NST == 2) {
            if (c + 1 >= NC) { CP_WAITN(0); } else { CP_WAITN(1); }
        } else {
            if (c + 1 >= NC)      { CP_WAITN(0); }
            else if (c + 2 >= NC) { CP_WAITN(1); }
            else                  { CP_WAITN(2); }
        }
        __syncthreads();

        const uint32_t sb = smb + (c % NST) * STAGE;
#pragma unroll
        for (int kh = 0; kh < 2; kh++) {
            const uint32_t kB = kh * 32;
            uint32_t aH[2][4], aL[2][4], bH[4][4];
            ldm4(aH[0], sb + aoff + kB);
            ldm4(aH[1], sb + aoff + 16 * 80 + kB);
#pragma unroll
            for (int np = 0; np < 4; np++)
                ldm4(bH[np], sb + 20480 + boff + np * 16 * 80 + kB);
            // pass 1: Ah * Bh
#pragma unroll
            for (int mt = 0; mt < 2; mt++)
#pragma unroll
                for (int np = 0; np < 4; np++) {
                    if (NPASS == 2) {
                        mma_fp16(acc[mt][np * 2 + 0], aH[mt], bH[np][0], bH[np][2]);
                        mma_fp16(acc[mt][np * 2 + 1], aH[mt], bH[np][1], bH[np][3]);
                    } else {
                        mma_bf16(acc[mt][np * 2 + 0], aH[mt], bH[np][0], bH[np][2]);
                        mma_bf16(acc[mt][np * 2 + 1], aH[mt], bH[np][1], bH[np][3]);
                    }
                }
            // pass 2: Al * Bh
            ldm4(aL[0], sb + 10240 + aoff + kB);
            ldm4(aL[1], sb + 10240 + aoff + 16 * 80 + kB);
#pragma unroll
            for (int mt = 0; mt < 2; mt++)
#pragma unroll
                for (int np = 0; np < 4; np++) {
                    if (NPASS == 2) {
                        mma_fp16(acc[mt][np * 2 + 0], aL[mt], bH[np][0], bH[np][2]);
                        mma_fp16(acc[mt][np * 2 + 1], aL[mt], bH[np][1], bH[np][3]);
                    } else {
                        mma_bf16(acc[mt][np * 2 + 0], aL[mt], bH[np][0], bH[np][2]);
                        mma_bf16(acc[mt][np * 2 + 1], aL[mt], bH[np][1], bH[np][3]);
                    }
                }
            // pass 3 (bf16 only): Ah * Bl
            if (NPASS == 3) {
#pragma unroll
                for (int np = 0; np < 4; np++) {
                    uint32_t bL[4];
                    ldm4(bL, sb + 30720 + boff + np * 16 * 80 + kB);
                    mma_bf16(acc[0][np * 2 + 0], aH[0], bL[0], bL[2]);
                    mma_bf16(acc[0][np * 2 + 1], aH[0], bL[1], bL[3]);
                    mma_bf16(acc[1][np * 2 + 0], aH[1], bL[0], bL[2]);
                    mma_bf16(acc[1][np * 2 + 1], aH[1], bL[1], bL[3]);
                }
            }
        }
        __syncthreads();
        if (c + NST < NC) issue(c + NST, (c + NST) % NST);
    }

    // -------- epilogue: acc -> smem fp32 staging (128x132) -> global --------
    float* fsm = reinterpret_cast<float*>(dynsmem);
    {
        const int g  = lane >> 2;
        const int tg = lane & 3;
#pragma unroll
        for (int mt = 0; mt < 2; mt++)
#pragma unroll
            for (int nt = 0; nt < 8; nt++) {
                const int r0 = wm + mt * 16 + g;
                const int cc = wn + nt * 8 + 2 * tg;
                *reinterpret_cast<float2*>(&fsm[r0 * 132 + cc]) =
                    make_float2(acc[mt][nt][0], acc[mt][nt][1]);
                *reinterpret_cast<float2*>(&fsm[(r0 + 8) * 132 + cc]) =
                    make_float2(acc[mt][nt][2], acc[mt][nt][3]);
            }
    }
    __syncthreads();

    if (MODE == M_V) {
        // transposed scatter: vt[h][r*64+d][j] (+ bias) bf16, coalesced along j
#pragma unroll 8
        for (int i = 0; i < 64; i++) {
            const int f = t + i * 256;
            const int m = f & 127;
            const int n = f >> 7;
            const int ng = n0 + n;
            float v = fsm[m * 132 + n] + bias[ng];
            const int h = ng >> 6, d = ng & 63;
            const int mg = m0 + m;
            const int r = mg >> 8, j = mg & 255;
            u16 hh, ll;
            split1(v, hh, ll);
            const size_t oi = ((size_t)h * PHEAD + r * 64 + d) * C_DIM + j;
            outH[oi] = hh; outL[oi] = ll;
        }
    } else {
#pragma unroll
        for (int i = 0; i < 16; i++) {
            const int f = t + i * 256;
            const int row = f >> 5;
            const int q   = f & 31;
            float4 v = *reinterpret_cast<const float4*>(&fsm[row * 132 + q * 4]);
            const int m = m0 + row;
            const int n = n0 + q * 4;
            if (MODE == M_SCORES) {
                *reinterpret_cast<float4*>(&outF[(size_t)m * C_DIM + n]) = v;
            } else if (MODE == M_PLAIN) {
                float4 bb = *reinterpret_cast<const float4*>(&bias[n]);
                v.x += bb.x; v.y += bb.y; v.z += bb.z; v.w += bb.w;
                *reinterpret_cast<float4*>(&outF[(size_t)m * E_DIM + n]) = v;
            } else if (MODE == M_QK) {
                float4 bb = *reinterpret_cast<const float4*>(&bias[n]);
                v.x = (v.x + bb.x) * alpha; v.y = (v.y + bb.y) * alpha;
                v.z = (v.z + bb.z) * alpha; v.w = (v.w + bb.w) * alpha;
                uint32_t h01, l01, h23, l23;
                split2(v.x, v.y, h01, l01);     // bf16 for scores GEMM
                split2(v.z, v.w, h23, l23);
                const int h = n >> 6, d = n & 63;
                const int r = m >> 8, ij = m & 255;
                const size_t oi = ((size_t)h * C_DIM + ij) * PHEAD + r * 64 + d;
                *reinterpret_cast<uint2*>(&outH[oi]) = make_uint2(h01, h23);
                *reinterpret_cast<uint2*>(&outL[oi]) = make_uint2(l01, l23);
            } else { // M_AV -> cb fp16 [(r*C+i)][hz*64+d]
                uint32_t h01, l01, h23, l23;
                splitH2(v.x, v.y, h01, l01);    // fp16 for output projection
                splitH2(v.z, v.w, h23, l23);
                const int r = n >> 6, d = n & 63;
                const size_t oi = ((size_t)r * C_DIM + m) * E_DIM + hz * 64 + d;
                *reinterpret_cast<uint2*>(&outH[oi]) = make_uint2(h01, h23);
                *reinterpret_cast<uint2*>(&outL[oi]) = make_uint2(l01, l23);
            }
        }
    }
}

// ---------------- softmax: reduce 16 partials, softmax, emit fp32 + bf16 ----------------
__global__ __launch_bounds__(256)
void softmax_kernel(const float* __restrict__ part, float* __restrict__ probs,
                    float* __restrict__ probs_out,
                    u16* __restrict__ pbh, u16* __restrict__ pbl)
{
    const int row = blockIdx.x;
    const int h = row >> 8;
    const int i = row & 255;
    const int j = threadIdx.x;

    float v = 0.0f;
#pragma unroll
    for (int s = 0; s < SPLIT_S; s++)
        v += part[((size_t)(h * SPLIT_S + s)) * (C_DIM * C_DIM) + (size_t)i * C_DIM + j];

    __shared__ float red[256];
    red[j] = v;
    __syncthreads();
#pragma unroll
    for (int off = 128; off > 0; off >>= 1) {
        if (j < off) red[j] = fmaxf(red[j], red[j + off]);
        __syncthreads();
    }
    const float mx = red[0];
    __syncthreads();
    const float e = expf(v - mx);
    red[j] = e;
    __syncthreads();
#pragma unroll
    for (int off = 128; off > 0; off >>= 1) {
        if (j < off) red[j] += red[j + off];
        __syncthreads();
    }
    const float p = e / red[0];

    const size_t idx = (size_t)row * C_DIM + j;
    probs[idx] = p;
    if (probs_out) probs_out[idx] = p;
    u16 hh, ll;
    split1(p, hh, ll);
    pbh[idx] = hh; pbl[idx] = ll;
}

// ---------------- launch ----------------
extern "C" void kernel_launch(void* const* d_in, const int* in_sizes, int n_in,
                              void* d_out, int out_size)
{
    const float* x  = (const float*)d_in[0];
    const float* Wq = (const float*)d_in[1];
    const float* bq = (const float*)d_in[2];
    const float* Wk = (const float*)d_in[3];
    const float* bk = (const float*)d_in[4];
    const float* Wv = (const float*)d_in[5];
    const float* bv = (const float*)d_in[6];
    const float* Wo = (const float*)d_in[7];
    const float* bo = (const float*)d_in[8];
    float* out = (float*)d_out;

    float* probs_out = nullptr;
    if ((size_t)out_size >= OUT_ELEMS + SCORES_ELEMS)
        probs_out = out + ((size_t)out_size - SCORES_ELEMS);

    u16 *xh, *xl, *wqh, *wql, *wkh, *wkl, *wvh, *wvl, *woh, *wol;
    u16 *qth, *qtl, *kth, *ktl, *vth, *vtl, *pbh, *pbl, *cbh, *cbl;
    float *part, *probs;
    cudaGetSymbolAddress((void**)&xh, g_xh);   cudaGetSymbolAddress((void**)&xl, g_xl);
    cudaGetSymbolAddress((void**)&wqh, g_wqh); cudaGetSymbolAddress((void**)&wql, g_wql);
    cudaGetSymbolAddress((void**)&wkh, g_wkh); cudaGetSymbolAddress((void**)&wkl, g_wkl);
    cudaGetSymbolAddress((void**)&wvh, g_wvh); cudaGetSymbolAddress((void**)&wvl, g_wvl);
    cudaGetSymbolAddress((void**)&woh, g_woh); cudaGetSymbolAddress((void**)&wol, g_wol);
    cudaGetSymbolAddress((void**)&qth, g_qth); cudaGetSymbolAddress((void**)&qtl, g_qtl);
    cudaGetSymbolAddress((void**)&kth, g_kth); cudaGetSymbolAddress((void**)&ktl, g_ktl);
    cudaGetSymbolAddress((void**)&vth, g_vth); cudaGetSymbolAddress((void**)&vtl, g_vtl);
    cudaGetSymbolAddress((void**)&pbh, g_pbh); cudaGetSymbolAddress((void**)&pbl, g_pbl);
    cudaGetSymbolAddress((void**)&cbh, g_cbh); cudaGetSymbolAddress((void**)&cbl, g_cbl);
    cudaGetSymbolAddress((void**)&part, g_part);
    cudaGetSymbolAddress((void**)&probs, g_probs);

    cudaFuncSetAttribute((const void*)hm_gemm<M_QK, 2>,     cudaFuncAttributeMaxDynamicSharedMemorySize, Cfg<2>::DYN);
    cudaFuncSetAttribute((const void*)hm_gemm<M_V, 2>,      cudaFuncAttributeMaxDynamicSharedMemorySize, Cfg<2>::DYN);
    cudaFuncSetAttribute((const void*)hm_gemm<M_PLAIN, 2>,  cudaFuncAttributeMaxDynamicSharedMemorySize, Cfg<2>::DYN);
    cudaFuncSetAttribute((const void*)hm_gemm<M_SCORES, 3>, cudaFuncAttributeMaxDynamicSharedMemorySize, Cfg<3>::DYN);
    cudaFuncSetAttribute((const void*)hm_gemm<M_AV, 3>,     cudaFuncAttributeMaxDynamicSharedMemorySize, Cfg<3>::DYN);

    const float scaling = (float)(1.0 / (8.0 * sqrt(128.0)));

    // input conversions (fp16 hi/lo)
    convert_splitH<<<1024, 256>>>(x,  xh,  xl,  OUT_ELEMS / 4);
    convert_splitH<<<288,  256>>>(Wq, wqh, wql, W_ELEMS / 4);
    convert_splitH<<<288,  256>>>(Wk, wkh, wkl, W_ELEMS / 4);
    convert_splitH<<<288,  256>>>(Wv, wvh, wvl, W_ELEMS / 4);
    convert_splitH<<<288,  256>>>(Wo, woh, wol, W_ELEMS / 4);

    dim3 blk(256);
    dim3 gproj(E_DIM / 128, MROWS / 128, 1);            // (6, 256)

    hm_gemm<M_QK, 2><<<gproj, blk, Cfg<2>::DYN>>>(xh, xl, wqh, wql, bq, nullptr, qth, qtl,
                                                  E_DIM, E_DIM, E_DIM, scaling);
    hm_gemm<M_QK, 2><<<gproj, blk, Cfg<2>::DYN>>>(xh, xl, wkh, wkl, bk, nullptr, kth, ktl,
                                                  E_DIM, E_DIM, E_DIM, 1.0f);
    hm_gemm<M_V, 2><<<gproj, blk, Cfg<2>::DYN>>>(xh, xl, wvh, wvl, bv, nullptr, vth, vtl,
                                                 E_DIM, E_DIM, E_DIM, 1.0f);

    dim3 gsc(C_DIM / 128, C_DIM / 128, H_DIM * SPLIT_S); // (2, 2, 192)
    hm_gemm<M_SCORES, 3><<<gsc, blk, Cfg<3>::DYN>>>(qth, qtl, kth, ktl, nullptr, part,
                                                    nullptr, nullptr,
                                                    PHEAD / SPLIT_S, PHEAD, PHEAD, 1.0f);

    softmax_kernel<<<H_DIM * C_DIM, 256>>>(part, probs, probs_out, pbh, pbl);

    dim3 gav(PHEAD / 128, C_DIM / 128, H_DIM);           // (64, 2, 12)
    hm_gemm<M_AV, 3><<<gav, blk, Cfg<3>::DYN>>>(pbh, pbl, vth, vtl, nullptr, nullptr,
                                                cbh, cbl, C_DIM, C_DIM, C_DIM, 1.0f);

    hm_gemm<M_PLAIN, 2><<<gproj, blk, Cfg<2>::DYN>>>(cbh, cbl, woh, wol, bo, out,
                                                     nullptr, nullptr, E_DIM, E_DIM, E_DIM, 1.0f);
}

// round 6
// speedup vs baseline: 1.5033x; 1.0330x over previous
#include <cuda_runtime.h>
#include <cuda_bf16.h>
#include <cuda_fp16.h>
#include <math.h>
#include <stdint.h>

#define R_DIM 128
#define C_DIM 256
#define E_DIM 768
#define H_DIM 12
#define DK_DIM 64
#define MROWS (R_DIM * C_DIM)            // 32768
#define PHEAD (R_DIM * DK_DIM)           // 8192
#define SPLIT_S 8
#define SCORES_ELEMS (H_DIM * C_DIM * C_DIM)   // 786432
#define OUT_ELEMS ((size_t)MROWS * E_DIM)      // 25165824
#define W_ELEMS (E_DIM * E_DIM)                // 589824

typedef unsigned short u16;

// ---------------- scratch ----------------
__device__ u16 g_xh[OUT_ELEMS],  g_xl[OUT_ELEMS];        // fp16 hi/lo
__device__ u16 g_wqh[W_ELEMS], g_wql[W_ELEMS];           // fp16
__device__ u16 g_wkh[W_ELEMS], g_wkl[W_ELEMS];
__device__ u16 g_wvh[W_ELEMS], g_wvl[W_ELEMS];
__device__ u16 g_woh[W_ELEMS], g_wol[W_ELEMS];
__device__ u16 g_qth[OUT_ELEMS], g_qtl[OUT_ELEMS];       // bf16 [h][i][r*64+d]
__device__ u16 g_kth[OUT_ELEMS], g_ktl[OUT_ELEMS];       // bf16 [h][j][r*64+d]
__device__ u16 g_vth[OUT_ELEMS], g_vtl[OUT_ELEMS];       // fp16 [h][r*64+d][j]
__device__ u16 g_pbh[SCORES_ELEMS], g_pbl[SCORES_ELEMS]; // fp16 probs [h][i][j]
__device__ u16 g_cbh[OUT_ELEMS], g_cbl[OUT_ELEMS];       // fp16 [(r*C+i)][h*64+d]
__device__ float g_part[(size_t)SPLIT_S * SCORES_ELEMS];
__device__ float g_probs[SCORES_ELEMS];

// ---------------- helpers ----------------
__device__ __forceinline__ uint32_t smem_u32(const void* p) {
    uint32_t a;
    asm("{ .reg .u64 t; cvta.to.shared.u64 t, %1; cvt.u32.u64 %0, t; }" : "=r"(a) : "l"(p));
    return a;
}

// bf16 split: hi = truncation, lo = RN residual; low 16 bits = x
__device__ __forceinline__ void split2(float x, float y, uint32_t& h, uint32_t& l) {
    uint32_t ux = __float_as_uint(x), uy = __float_as_uint(y);
    asm("prmt.b32 %0, %1, %2, 0x7632;" : "=r"(h) : "r"(ux), "r"(uy));
    float hx = __uint_as_float(ux & 0xffff0000u);
    float hy = __uint_as_float(uy & 0xffff0000u);
    asm("cvt.rn.bf16x2.f32 %0, %1, %2;" : "=r"(l) : "f"(y - hy), "f"(x - hx));
}
// fp16 split pair
__device__ __forceinline__ void splitH2(float x, float y, uint32_t& h, uint32_t& l) {
    __half2 h2 = __floats2half2_rn(x, y);
    float2 hf = __half22float2(h2);
    __half2 l2 = __floats2half2_rn(x - hf.x, y - hf.y);
    h = *reinterpret_cast<uint32_t*>(&h2);
    l = *reinterpret_cast<uint32_t*>(&l2);
}
// fp16 split scalar
__device__ __forceinline__ void splitH1(float x, u16& h, u16& l) {
    __half hh = __float2half_rn(x);
    h = *reinterpret_cast<u16*>(&hh);
    __half ll = __float2half_rn(x - __half2float(hh));
    l = *reinterpret_cast<u16*>(&ll);
}

__device__ __forceinline__ void ldm4(uint32_t r[4], uint32_t addr) {
    asm volatile("ldmatrix.sync.aligned.m8n8.x4.shared.b16 {%0,%1,%2,%3}, [%4];"
                 : "=r"(r[0]), "=r"(r[1]), "=r"(r[2]), "=r"(r[3]) : "r"(addr));
}
__device__ __forceinline__ void mma_bf16(float c[4], const uint32_t a[4],
                                         uint32_t b0, uint32_t b1) {
    asm volatile("mma.sync.aligned.m16n8k16.row.col.f32.bf16.bf16.f32 "
        "{%0,%1,%2,%3}, {%4,%5,%6,%7}, {%8,%9}, {%0,%1,%2,%3};"
        : "+f"(c[0]), "+f"(c[1]), "+f"(c[2]), "+f"(c[3])
        : "r"(a[0]), "r"(a[1]), "r"(a[2]), "r"(a[3]), "r"(b0), "r"(b1));
}
__device__ __forceinline__ void mma_fp16(float c[4], const uint32_t a[4],
                                         uint32_t b0, uint32_t b1) {
    asm volatile("mma.sync.aligned.m16n8k16.row.col.f32.f16.f16.f32 "
        "{%0,%1,%2,%3}, {%4,%5,%6,%7}, {%8,%9}, {%0,%1,%2,%3};"
        : "+f"(c[0]), "+f"(c[1]), "+f"(c[2]), "+f"(c[3])
        : "r"(a[0]), "r"(a[1]), "r"(a[2]), "r"(a[3]), "r"(b0), "r"(b1));
}
#define CP16(dst, src) \
    asm volatile("cp.async.cg.shared.global [%0], [%1], 16;" :: "r"(dst), "l"(src) : "memory")
#define CP_COMMIT() asm volatile("cp.async.commit_group;" ::: "memory")
#define CP_WAITN(n) asm volatile("cp.async.wait_group %0;" :: "n"(n) : "memory")

// ---------------- input convert: fp32 -> fp16 hi/lo ----------------
__global__ __launch_bounds__(256)
void convert_splitH(const float* __restrict__ src, u16* __restrict__ h,
                    u16* __restrict__ l, int n4)
{
    for (int i = blockIdx.x * blockDim.x + threadIdx.x; i < n4; i += gridDim.x * blockDim.x) {
        float4 v = reinterpret_cast<const float4*>(src)[i];
        uint32_t h01, l01, h23, l23;
        splitH2(v.x, v.y, h01, l01);
        splitH2(v.z, v.w, h23, l23);
        reinterpret_cast<uint2*>(h)[i] = make_uint2(h01, h23);
        reinterpret_cast<uint2*>(l)[i] = make_uint2(l01, l23);
    }
}

// ---------------- HMMA GEMM: C = A(MxK) * B(NxK)^T ----------------
// NPASS=2: fp16 (AhBh + AlBh), 3-stage.  NPASS=3: bf16 (AhBh + AlBh + AhBl), 2-stage.
// Single __syncthreads per chunk (CUTLASS multistage ordering).
enum { M_PLAIN = 0, M_QK = 1, M_V = 2, M_SCORES = 3, M_AV = 4 };

template<int NPASS> struct Cfg;
template<> struct Cfg<2> { static const int STAGE = 30720, NST = 3, DYN = 92160; };
template<> struct Cfg<3> { static const int STAGE = 40960, NST = 2, DYN = 81920; };

template<int MODE, int NPASS>
__global__ __launch_bounds__(256, 2)
void hm_gemm(const u16* __restrict__ Ah, const u16* __restrict__ Al,
             const u16* __restrict__ Bh, const u16* __restrict__ Bl,
             const float* __restrict__ bias, float* __restrict__ outF,
             u16* __restrict__ outH, u16* __restrict__ outL,
             int K, int lda, int ldb, float alpha)
{
    extern __shared__ char dynsmem[];
    const int t    = threadIdx.x;
    const int lane = t & 31;
    const int wid  = t >> 5;
    const int wm   = (wid & 3) * 32;
    const int wn   = (wid >> 2) * 64;
    const int m0   = blockIdx.y * 128;
    const int n0   = blockIdx.x * 128;
    const int STAGE = Cfg<NPASS>::STAGE;
    const int NST   = Cfg<NPASS>::NST;

    int hz = 0;
    if (MODE == M_SCORES) {
        const int z = blockIdx.z;
        const int h = z >> 3, s = z & 7;
        const size_t off = (size_t)h * C_DIM * PHEAD + (size_t)s * (PHEAD / SPLIT_S);
        Ah += off; Al += off; Bh += off; Bl += off;
        outF += (size_t)z * (C_DIM * C_DIM);
    } else if (MODE == M_AV) {
        hz = blockIdx.z;
        const size_t ao = (size_t)hz * C_DIM * C_DIM;
        const size_t bo = (size_t)hz * PHEAD * C_DIM;
        Ah += ao; Al += ao; Bh += bo; Bl += bo;
    }

    const uint32_t smb = smem_u32(dynsmem);
    const int NC = K >> 5;

    auto issue = [&](int c, int s) {
        const int kk = c << 5;
        const uint32_t sb = smb + s * STAGE;
#pragma unroll
        for (int it = 0; it < 2; it++) {
            const int f   = t + it * 256;      // 0..511
            const int row = f >> 2;            // 0..127
            const int k8  = f & 3;
            const uint32_t so = (uint32_t)(row * 80 + k8 * 16);
            const size_t ga = (size_t)(m0 + row) * lda + kk + k8 * 8;
            const size_t gb = (size_t)(n0 + row) * ldb + kk + k8 * 8;
            CP16(sb +     0 + so, Ah + ga);
            CP16(sb + 10240 + so, Al + ga);
            CP16(sb + 20480 + so, Bh + gb);
            if (NPASS == 3) CP16(sb + 30720 + so, Bl + gb);
        }
        CP_COMMIT();
    };

    float acc[2][8][4];
#pragma unroll
    for (int mt = 0; mt < 2; mt++)
#pragma unroll
        for (int nt = 0; nt < 8; nt++)
#pragma unroll
            for (int e = 0; e < 4; e++) acc[mt][nt][e] = 0.0f;

    const uint32_t ro = (uint32_t)(((lane >> 3) & 1) * 8 + (lane & 7));
    const uint32_t co = (lane & 16) ? 16u : 0u;
    const uint32_t aoff = (uint32_t)(wm + ro) * 80 + co;
    const uint32_t boff = (uint32_t)(wn + ro) * 80 + co;

    // prologue: NST-1 chunks in flight
    issue(0, 0);
    if (NST == 3 && NC > 1) issue(1, 1);

    for (int c = 0; c < NC; c++) {
        if (NST == 3) {
            if (c + 1 >= NC) { CP_WAITN(0); } else { CP_WAITN(1); }
        } else {
            CP_WAITN(0);
        }
        __syncthreads();
        // issue chunk c+NST-1 into the buffer consumed at iteration c-1 (safe post-sync)
        if (c + NST - 1 < NC) issue(c + NST - 1, (c + NST - 1) % NST);

        const uint32_t sb = smb + (c % NST) * STAGE;
#pragma unroll
        for (int kh = 0; kh < 2; kh++) {
            const uint32_t kB = kh * 32;
            uint32_t aH[2][4], aL[2][4], bH[4][4];
            ldm4(aH[0], sb + aoff + kB);
            ldm4(aH[1], sb + aoff + 16 * 80 + kB);
#pragma unroll
            for (int np = 0; np < 4; np++)
                ldm4(bH[np], sb + 20480 + boff + np * 16 * 80 + kB);
            // pass 1: Ah * Bh
#pragma unroll
            for (int mt = 0; mt < 2; mt++)
#pragma unroll
                for (int np = 0; np < 4; np++) {
                    if (NPASS == 2) {
                        mma_fp16(acc[mt][np * 2 + 0], aH[mt], bH[np][0], bH[np][2]);
                        mma_fp16(acc[mt][np * 2 + 1], aH[mt], bH[np][1], bH[np][3]);
                    } else {
                        mma_bf16(acc[mt][np * 2 + 0], aH[mt], bH[np][0], bH[np][2]);
                        mma_bf16(acc[mt][np * 2 + 1], aH[mt], bH[np][1], bH[np][3]);
                    }
                }
            // pass 2: Al * Bh
            ldm4(aL[0], sb + 10240 + aoff + kB);
            ldm4(aL[1], sb + 10240 + aoff + 16 * 80 + kB);
#pragma unroll
            for (int mt = 0; mt < 2; mt++)
#pragma unroll
                for (int np = 0; np < 4; np++) {
                    if (NPASS == 2) {
                        mma_fp16(acc[mt][np * 2 + 0], aL[mt], bH[np][0], bH[np][2]);
                        mma_fp16(acc[mt][np * 2 + 1], aL[mt], bH[np][1], bH[np][3]);
                    } else {
                        mma_bf16(acc[mt][np * 2 + 0], aL[mt], bH[np][0], bH[np][2]);
                        mma_bf16(acc[mt][np * 2 + 1], aL[mt], bH[np][1], bH[np][3]);
                    }
                }
            // pass 3 (bf16 only): Ah * Bl
            if (NPASS == 3) {
#pragma unroll
                for (int np = 0; np < 4; np++) {
                    uint32_t bL[4];
                    ldm4(bL, sb + 30720 + boff + np * 16 * 80 + kB);
                    mma_bf16(acc[0][np * 2 + 0], aH[0], bL[0], bL[2]);
                    mma_bf16(acc[0][np * 2 + 1], aH[0], bL[1], bL[3]);
                    mma_bf16(acc[1][np * 2 + 0], aH[1], bL[0], bL[2]);
                    mma_bf16(acc[1][np * 2 + 1], aH[1], bL[1], bL[3]);
                }
            }
        }
        // no trailing sync — next iteration's top barrier provides it
    }
    __syncthreads();   // protect smem reuse by the epilogue

    // -------- epilogue: acc -> smem fp32 staging (128x132) -> global --------
    float* fsm = reinterpret_cast<float*>(dynsmem);
    {
        const int g  = lane >> 2;
        const int tg = lane & 3;
#pragma unroll
        for (int mt = 0; mt < 2; mt++)
#pragma unroll
            for (int nt = 0; nt < 8; nt++) {
                const int r0 = wm + mt * 16 + g;
                const int cc = wn + nt * 8 + 2 * tg;
                *reinterpret_cast<float2*>(&fsm[r0 * 132 + cc]) =
                    make_float2(acc[mt][nt][0], acc[mt][nt][1]);
                *reinterpret_cast<float2*>(&fsm[(r0 + 8) * 132 + cc]) =
                    make_float2(acc[mt][nt][2], acc[mt][nt][3]);
            }
    }
    __syncthreads();

    if (MODE == M_V) {
        // transposed scatter: vt[h][r*64+d][j] (+ bias) fp16, coalesced along j
#pragma unroll 8
        for (int i = 0; i < 64; i++) {
            const int f = t + i * 256;
            const int m = f & 127;
            const int n = f >> 7;
            const int ng = n0 + n;
            float v = fsm[m * 132 + n] + bias[ng];
            const int h = ng >> 6, d = ng & 63;
            const int mg = m0 + m;
            const int r = mg >> 8, j = mg & 255;
            u16 hh, ll;
            splitH1(v, hh, ll);
            const size_t oi = ((size_t)h * PHEAD + r * 64 + d) * C_DIM + j;
            outH[oi] = hh; outL[oi] = ll;
        }
    } else {
#pragma unroll
        for (int i = 0; i < 16; i++) {
            const int f = t + i * 256;
            const int row = f >> 5;
            const int q   = f & 31;
            float4 v = *reinterpret_cast<const float4*>(&fsm[row * 132 + q * 4]);
            const int m = m0 + row;
            const int n = n0 + q * 4;
            if (MODE == M_SCORES) {
                *reinterpret_cast<float4*>(&outF[(size_t)m * C_DIM + n]) = v;
            } else if (MODE == M_PLAIN) {
                float4 bb = *reinterpret_cast<const float4*>(&bias[n]);
                v.x += bb.x; v.y += bb.y; v.z += bb.z; v.w += bb.w;
                *reinterpret_cast<float4*>(&outF[(size_t)m * E_DIM + n]) = v;
            } else if (MODE == M_QK) {
                float4 bb = *reinterpret_cast<const float4*>(&bias[n]);
                v.x = (v.x + bb.x) * alpha; v.y = (v.y + bb.y) * alpha;
                v.z = (v.z + bb.z) * alpha; v.w = (v.w + bb.w) * alpha;
                uint32_t h01, l01, h23, l23;
                split2(v.x, v.y, h01, l01);     // bf16 for scores GEMM
                split2(v.z, v.w, h23, l23);
                const int h = n >> 6, d = n & 63;
                const int r = m >> 8, ij = m & 255;
                const size_t oi = ((size_t)h * C_DIM + ij) * PHEAD + r * 64 + d;
                *reinterpret_cast<uint2*>(&outH[oi]) = make_uint2(h01, h23);
                *reinterpret_cast<uint2*>(&outL[oi]) = make_uint2(l01, l23);
            } else { // M_AV -> cb fp16 [(r*C+i)][hz*64+d]
                uint32_t h01, l01, h23, l23;
                splitH2(v.x, v.y, h01, l01);
                splitH2(v.z, v.w, h23, l23);
                const int r = n >> 6, d = n & 63;
                const size_t oi = ((size_t)r * C_DIM + m) * E_DIM + hz * 64 + d;
                *reinterpret_cast<uint2*>(&outH[oi]) = make_uint2(h01, h23);
                *reinterpret_cast<uint2*>(&outL[oi]) = make_uint2(l01, l23);
            }
        }
    }
}

// ---------------- softmax: reduce partials, softmax, emit fp32 + fp16 ----------------
__global__ __launch_bounds__(256)
void softmax_kernel(const float* __restrict__ part, float* __restrict__ probs,
                    float* __restrict__ probs_out,
                    u16* __restrict__ pbh, u16* __restrict__ pbl)
{
    const int row = blockIdx.x;
    const int h = row >> 8;
    const int i = row & 255;
    const int j = threadIdx.x;

    float v = 0.0f;
#pragma unroll
    for (int s = 0; s < SPLIT_S; s++)
        v += part[((size_t)(h * SPLIT_S + s)) * (C_DIM * C_DIM) + (size_t)i * C_DIM + j];

    __shared__ float red[256];
    red[j] = v;
    __syncthreads();
#pragma unroll
    for (int off = 128; off > 0; off >>= 1) {
        if (j < off) red[j] = fmaxf(red[j], red[j + off]);
        __syncthreads();
    }
    const float mx = red[0];
    __syncthreads();
    const float e = expf(v - mx);
    red[j] = e;
    __syncthreads();
#pragma unroll
    for (int off = 128; off > 0; off >>= 1) {
        if (j < off) red[j] += red[j + off];
        __syncthreads();
    }
    const float p = e / red[0];

    const size_t idx = (size_t)row * C_DIM + j;
    probs[idx] = p;
    if (probs_out) probs_out[idx] = p;
    u16 hh, ll;
    splitH1(p, hh, ll);
    pbh[idx] = hh; pbl[idx] = ll;
}

// ---------------- launch ----------------
extern "C" void kernel_launch(void* const* d_in, const int* in_sizes, int n_in,
                              void* d_out, int out_size)
{
    const float* x  = (const float*)d_in[0];
    const float* Wq = (const float*)d_in[1];
    const float* bq = (const float*)d_in[2];
    const float* Wk = (const float*)d_in[3];
    const float* bk = (const float*)d_in[4];
    const float* Wv = (const float*)d_in[5];
    const float* bv = (const float*)d_in[6];
    const float* Wo = (const float*)d_in[7];
    const float* bo = (const float*)d_in[8];
    float* out = (float*)d_out;

    float* probs_out = nullptr;
    if ((size_t)out_size >= OUT_ELEMS + SCORES_ELEMS)
        probs_out = out + ((size_t)out_size - SCORES_ELEMS);

    u16 *xh, *xl, *wqh, *wql, *wkh, *wkl, *wvh, *wvl, *woh, *wol;
    u16 *qth, *qtl, *kth, *ktl, *vth, *vtl, *pbh, *pbl, *cbh, *cbl;
    float *part, *probs;
    cudaGetSymbolAddress((void**)&xh, g_xh);   cudaGetSymbolAddress((void**)&xl, g_xl);
    cudaGetSymbolAddress((void**)&wqh, g_wqh); cudaGetSymbolAddress((void**)&wql, g_wql);
    cudaGetSymbolAddress((void**)&wkh, g_wkh); cudaGetSymbolAddress((void**)&wkl, g_wkl);
    cudaGetSymbolAddress((void**)&wvh, g_wvh); cudaGetSymbolAddress((void**)&wvl, g_wvl);
    cudaGetSymbolAddress((void**)&woh, g_woh); cudaGetSymbolAddress((void**)&wol, g_wol);
    cudaGetSymbolAddress((void**)&qth, g_qth); cudaGetSymbolAddress((void**)&qtl, g_qtl);
    cudaGetSymbolAddress((void**)&kth, g_kth); cudaGetSymbolAddress((void**)&ktl, g_ktl);
    cudaGetSymbolAddress((void**)&vth, g_vth); cudaGetSymbolAddress((void**)&vtl, g_vtl);
    cudaGetSymbolAddress((void**)&pbh, g_pbh); cudaGetSymbolAddress((void**)&pbl, g_pbl);
    cudaGetSymbolAddress((void**)&cbh, g_cbh); cudaGetSymbolAddress((void**)&cbl, g_cbl);
    cudaGetSymbolAddress((void**)&part, g_part);
    cudaGetSymbolAddress((void**)&probs, g_probs);

    cudaFuncSetAttribute((const void*)hm_gemm<M_QK, 2>,     cudaFuncAttributeMaxDynamicSharedMemorySize, Cfg<2>::DYN);
    cudaFuncSetAttribute((const void*)hm_gemm<M_V, 2>,      cudaFuncAttributeMaxDynamicSharedMemorySize, Cfg<2>::DYN);
    cudaFuncSetAttribute((const void*)hm_gemm<M_PLAIN, 2>,  cudaFuncAttributeMaxDynamicSharedMemorySize, Cfg<2>::DYN);
    cudaFuncSetAttribute((const void*)hm_gemm<M_AV, 2>,     cudaFuncAttributeMaxDynamicSharedMemorySize, Cfg<2>::DYN);
    cudaFuncSetAttribute((const void*)hm_gemm<M_SCORES, 3>, cudaFuncAttributeMaxDynamicSharedMemorySize, Cfg<3>::DYN);

    const float scaling = (float)(1.0 / (8.0 * sqrt(128.0)));

    // input conversions (fp16 hi/lo)
    convert_splitH<<<1024, 256>>>(x,  xh,  xl,  OUT_ELEMS / 4);
    convert_splitH<<<288,  256>>>(Wq, wqh, wql, W_ELEMS / 4);
    convert_splitH<<<288,  256>>>(Wk, wkh, wkl, W_ELEMS / 4);
    convert_splitH<<<288,  256>>>(Wv, wvh, wvl, W_ELEMS / 4);
    convert_splitH<<<288,  256>>>(Wo, woh, wol, W_ELEMS / 4);

    dim3 blk(256);
    dim3 gproj(E_DIM / 128, MROWS / 128, 1);            // (6, 256)

    hm_gemm<M_QK, 2><<<gproj, blk, Cfg<2>::DYN>>>(xh, xl, wqh, wql, bq, nullptr, qth, qtl,
                                                  E_DIM, E_DIM, E_DIM, scaling);
    hm_gemm<M_QK, 2><<<gproj, blk, Cfg<2>::DYN>>>(xh, xl, wkh, wkl, bk, nullptr, kth, ktl,
                                                  E_DIM, E_DIM, E_DIM, 1.0f);
    hm_gemm<M_V, 2><<<gproj, blk, Cfg<2>::DYN>>>(xh, xl, wvh, wvl, bv, nullptr, vth, vtl,
                                                 E_DIM, E_DIM, E_DIM, 1.0f);

    dim3 gsc(C_DIM / 128, C_DIM / 128, H_DIM * SPLIT_S); // (2, 2, 96)
    hm_gemm<M_SCORES, 3><<<gsc, blk, Cfg<3>::DYN>>>(qth, qtl, kth, ktl, nullptr, part,
                                                    nullptr, nullptr,
                                                    PHEAD / SPLIT_S, PHEAD, PHEAD, 1.0f);

    softmax_kernel<<<H_DIM * C_DIM, 256>>>(part, probs, probs_out, pbh, pbl);

    dim3 gav(PHEAD / 128, C_DIM / 128, H_DIM);           // (64, 2, 12)
    hm_gemm<M_AV, 2><<<gav, blk, Cfg<2>::DYN>>>(pbh, pbl, vth, vtl, nullptr, nullptr,
                                                cbh, cbl, C_DIM, C_DIM, C_DIM, 1.0f);

    hm_gemm<M_PLAIN, 2><<<gproj, blk, Cfg<2>::DYN>>>(cbh, cbl, woh, wol, bo, out,
                                                     nullptr, nullptr, E_DIM, E_DIM, E_DIM, 1.0f);
}

// round 7
// speedup vs baseline: 1.5265x; 1.0155x over previous
#include <cuda_runtime.h>
#include <cuda_bf16.h>
#include <cuda_fp16.h>
#include <math.h>
#include <stdint.h>

#define R_DIM 128
#define C_DIM 256
#define E_DIM 768
#define H_DIM 12
#define DK_DIM 64
#define MROWS (R_DIM * C_DIM)            // 32768
#define PHEAD (R_DIM * DK_DIM)           // 8192
#define SPLIT_S 16
#define SCORES_ELEMS (H_DIM * C_DIM * C_DIM)   // 786432
#define OUT_ELEMS ((size_t)MROWS * E_DIM)      // 25165824
#define W_ELEMS (E_DIM * E_DIM)                // 589824

typedef unsigned short u16;

// ---------------- scratch ----------------
__device__ u16 g_xh[OUT_ELEMS],  g_xl[OUT_ELEMS];        // fp16 hi/lo
__device__ u16 g_wfh[3 * W_ELEMS], g_wfl[3 * W_ELEMS];   // fused [Wq;Wk;Wv] fp16
__device__ u16 g_woh[W_ELEMS], g_wol[W_ELEMS];
__device__ u16 g_qth[OUT_ELEMS], g_qtl[OUT_ELEMS];       // fp16 [h][i][r*64+d] (unscaled)
__device__ u16 g_kth[OUT_ELEMS], g_ktl[OUT_ELEMS];       // fp16 [h][j][r*64+d]
__device__ u16 g_vth[OUT_ELEMS], g_vtl[OUT_ELEMS];       // fp16 [h][r*64+d][j]
__device__ u16 g_pbh[SCORES_ELEMS], g_pbl[SCORES_ELEMS]; // fp16 probs [h][i][j]
__device__ u16 g_cbh[OUT_ELEMS], g_cbl[OUT_ELEMS];       // fp16 [(r*C+i)][h*64+d]
__device__ float g_part[(size_t)SPLIT_S * SCORES_ELEMS];
__device__ float g_probs[SCORES_ELEMS];

// ---------------- helpers ----------------
__device__ __forceinline__ uint32_t smem_u32(const void* p) {
    uint32_t a;
    asm("{ .reg .u64 t; cvta.to.shared.u64 t, %1; cvt.u32.u64 %0, t; }" : "=r"(a) : "l"(p));
    return a;
}
// fp16 split pair
__device__ __forceinline__ void splitH2(float x, float y, uint32_t& h, uint32_t& l) {
    __half2 h2 = __floats2half2_rn(x, y);
    float2 hf = __half22float2(h2);
    __half2 l2 = __floats2half2_rn(x - hf.x, y - hf.y);
    h = *reinterpret_cast<uint32_t*>(&h2);
    l = *reinterpret_cast<uint32_t*>(&l2);
}
// fp16 split scalar
__device__ __forceinline__ void splitH1(float x, u16& h, u16& l) {
    __half hh = __float2half_rn(x);
    h = *reinterpret_cast<u16*>(&hh);
    __half ll = __float2half_rn(x - __half2float(hh));
    l = *reinterpret_cast<u16*>(&ll);
}

__device__ __forceinline__ void ldm4(uint32_t r[4], uint32_t addr) {
    asm volatile("ldmatrix.sync.aligned.m8n8.x4.shared.b16 {%0,%1,%2,%3}, [%4];"
                 : "=r"(r[0]), "=r"(r[1]), "=r"(r[2]), "=r"(r[3]) : "r"(addr));
}
// fp16 mma, f32 accumulator
__device__ __forceinline__ void mma_f32(float c[4], const uint32_t a[4],
                                        uint32_t b0, uint32_t b1) {
    asm volatile("mma.sync.aligned.m16n8k16.row.col.f32.f16.f16.f32 "
        "{%0,%1,%2,%3}, {%4,%5,%6,%7}, {%8,%9}, {%0,%1,%2,%3};"
        : "+f"(c[0]), "+f"(c[1]), "+f"(c[2]), "+f"(c[3])
        : "r"(a[0]), "r"(a[1]), "r"(a[2]), "r"(a[3]), "r"(b0), "r"(b1));
}
// fp16 mma, f16 accumulator (2 packed regs)
__device__ __forceinline__ void mma_f16(uint32_t c[2], const uint32_t a[4],
                                        uint32_t b0, uint32_t b1) {
    asm volatile("mma.sync.aligned.m16n8k16.row.col.f16.f16.f16.f16 "
        "{%0,%1}, {%2,%3,%4,%5}, {%6,%7}, {%0,%1};"
        : "+r"(c[0]), "+r"(c[1])
        : "r"(a[0]), "r"(a[1]), "r"(a[2]), "r"(a[3]), "r"(b0), "r"(b1));
}
#define CP16(dst, src) \
    asm volatile("cp.async.cg.shared.global [%0], [%1], 16;" :: "r"(dst), "l"(src) : "memory")
#define CP_COMMIT() asm volatile("cp.async.commit_group;" ::: "memory")
#define CP_WAITN(n) asm volatile("cp.async.wait_group %0;" :: "n"(n) : "memory")

// ---------------- input convert: fp32 -> fp16 hi/lo ----------------
__global__ __launch_bounds__(256)
void convert_splitH(const float* __restrict__ src, u16* __restrict__ h,
                    u16* __restrict__ l, int n4)
{
    for (int i = blockIdx.x * blockDim.x + threadIdx.x; i < n4; i += gridDim.x * blockDim.x) {
        float4 v = reinterpret_cast<const float4*>(src)[i];
        uint32_t h01, l01, h23, l23;
        splitH2(v.x, v.y, h01, l01);
        splitH2(v.z, v.w, h23, l23);
        reinterpret_cast<uint2*>(h)[i] = make_uint2(h01, h23);
        reinterpret_cast<uint2*>(l)[i] = make_uint2(l01, l23);
    }
}

// ---------------- HMMA GEMM: C = A(MxK) * B(NxK)^T ----------------
// Passes: AhBh -> f32 acc, AlBh -> f16 acc, (3-pass: AhBl -> f16 acc).
enum { M_PLAIN = 0, M_QKV = 1, M_SCORES = 2, M_AV = 3 };

template<int NPASS> struct Cfg;
template<> struct Cfg<2> { static const int STAGE = 30720, NST = 3, DYN = 92160; };
template<> struct Cfg<3> { static const int STAGE = 40960, NST = 2, DYN = 81920; };

template<int MODE, int NPASS>
__global__ __launch_bounds__(256, 2)
void hm_gemm(const u16* __restrict__ Ah, const u16* __restrict__ Al,
             const u16* __restrict__ Bh, const u16* __restrict__ Bl,
             const float* __restrict__ bias, const float* __restrict__ bias2,
             const float* __restrict__ bias3,
             float* __restrict__ outF,
             u16* __restrict__ outH,  u16* __restrict__ outL,
             u16* __restrict__ outH2, u16* __restrict__ outL2,
             u16* __restrict__ outH3, u16* __restrict__ outL3,
             int K, int lda, int ldb)
{
    extern __shared__ char dynsmem[];
    const int t    = threadIdx.x;
    const int lane = t & 31;
    const int wid  = t >> 5;
    const int wm   = (wid & 3) * 32;
    const int wn   = (wid >> 2) * 64;
    const int m0   = blockIdx.y * 128;
    const int n0   = blockIdx.x * 128;
    const int STAGE = Cfg<NPASS>::STAGE;
    const int NST   = Cfg<NPASS>::NST;

    int hz = 0;
    if (MODE == M_SCORES) {
        const int z = blockIdx.z;
        const int h = z >> 4, s = z & 15;
        const size_t off = (size_t)h * C_DIM * PHEAD + (size_t)s * (PHEAD / SPLIT_S);
        Ah += off; Al += off; Bh += off; Bl += off;
        outF += (size_t)z * (C_DIM * C_DIM);
    } else if (MODE == M_AV) {
        hz = blockIdx.z;
        const size_t ao = (size_t)hz * C_DIM * C_DIM;
        const size_t bo = (size_t)hz * PHEAD * C_DIM;
        Ah += ao; Al += ao; Bh += bo; Bl += bo;
    }

    const uint32_t smb = smem_u32(dynsmem);
    const int NC = K >> 5;

    auto issue = [&](int c, int s) {
        const int kk = c << 5;
        const uint32_t sb = smb + s * STAGE;
#pragma unroll
        for (int it = 0; it < 2; it++) {
            const int f   = t + it * 256;      // 0..511
            const int row = f >> 2;            // 0..127
            const int k8  = f & 3;
            const uint32_t so = (uint32_t)(row * 80 + k8 * 16);
            const size_t ga = (size_t)(m0 + row) * lda + kk + k8 * 8;
            const size_t gb = (size_t)(n0 + row) * ldb + kk + k8 * 8;
            CP16(sb +     0 + so, Ah + ga);
            CP16(sb + 10240 + so, Al + ga);
            CP16(sb + 20480 + so, Bh + gb);
            if (NPASS == 3) CP16(sb + 30720 + so, Bl + gb);
        }
        CP_COMMIT();
    };

    float    acc[2][8][4];
    uint32_t a16[2][8][2];
#pragma unroll
    for (int mt = 0; mt < 2; mt++)
#pragma unroll
        for (int nt = 0; nt < 8; nt++) {
#pragma unroll
            for (int e = 0; e < 4; e++) acc[mt][nt][e] = 0.0f;
            a16[mt][nt][0] = 0u; a16[mt][nt][1] = 0u;
        }

    const uint32_t ro = (uint32_t)(((lane >> 3) & 1) * 8 + (lane & 7));
    const uint32_t co = (lane & 16) ? 16u : 0u;
    const uint32_t aoff = (uint32_t)(wm + ro) * 80 + co;
    const uint32_t boff = (uint32_t)(wn + ro) * 80 + co;

    issue(0, 0);
    if (NST == 3 && NC > 1) issue(1, 1);

    for (int c = 0; c < NC; c++) {
        if (NST == 3) {
            if (c + 1 >= NC) { CP_WAITN(0); } else { CP_WAITN(1); }
        } else {
            CP_WAITN(0);
        }
        __syncthreads();
        if (c + NST - 1 < NC) issue(c + NST - 1, (c + NST - 1) % NST);

        const uint32_t sb = smb + (c % NST) * STAGE;
#pragma unroll
        for (int kh = 0; kh < 2; kh++) {
            const uint32_t kB = kh * 32;
            uint32_t aH[2][4], aL[2][4], bH[4][4];
            ldm4(aH[0], sb + aoff + kB);
            ldm4(aH[1], sb + aoff + 16 * 80 + kB);
#pragma unroll
            for (int np = 0; np < 4; np++)
                ldm4(bH[np], sb + 20480 + boff + np * 16 * 80 + kB);
            // pass 1: Ah*Bh -> f32 acc
#pragma unroll
            for (int mt = 0; mt < 2; mt++)
#pragma unroll
                for (int np = 0; np < 4; np++) {
                    mma_f32(acc[mt][np * 2 + 0], aH[mt], bH[np][0], bH[np][2]);
                    mma_f32(acc[mt][np * 2 + 1], aH[mt], bH[np][1], bH[np][3]);
                }
            // pass 2: Al*Bh -> f16 acc
            ldm4(aL[0], sb + 10240 + aoff + kB);
            ldm4(aL[1], sb + 10240 + aoff + 16 * 80 + kB);
#pragma unroll
            for (int mt = 0; mt < 2; mt++)
#pragma unroll
                for (int np = 0; np < 4; np++) {
                    mma_f16(a16[mt][np * 2 + 0], aL[mt], bH[np][0], bH[np][2]);
                    mma_f16(a16[mt][np * 2 + 1], aL[mt], bH[np][1], bH[np][3]);
                }
            // pass 3 (scores): Ah*Bl -> f16 acc
            if (NPASS == 3) {
#pragma unroll
                for (int np = 0; np < 4; np++) {
                    uint32_t bL[4];
                    ldm4(bL, sb + 30720 + boff + np * 16 * 80 + kB);
                    mma_f16(a16[0][np * 2 + 0], aH[0], bL[0], bL[2]);
                    mma_f16(a16[0][np * 2 + 1], aH[0], bL[1], bL[3]);
                    mma_f16(a16[1][np * 2 + 0], aH[1], bL[0], bL[2]);
                    mma_f16(a16[1][np * 2 + 1], aH[1], bL[1], bL[3]);
                }
            }
        }
    }
    __syncthreads();   // protect smem reuse by the epilogue

    // fold f16 acc into f32 acc
#pragma unroll
    for (int mt = 0; mt < 2; mt++)
#pragma unroll
        for (int nt = 0; nt < 8; nt++) {
            float2 p0 = __half22float2(*reinterpret_cast<__half2*>(&a16[mt][nt][0]));
            float2 p1 = __half22float2(*reinterpret_cast<__half2*>(&a16[mt][nt][1]));
            acc[mt][nt][0] += p0.x; acc[mt][nt][1] += p0.y;
            acc[mt][nt][2] += p1.x; acc[mt][nt][3] += p1.y;
        }

    // -------- epilogue: acc -> smem fp32 staging (128x132) -> global --------
    float* fsm = reinterpret_cast<float*>(dynsmem);
    {
        const int g  = lane >> 2;
        const int tg = lane & 3;
#pragma unroll
        for (int mt = 0; mt < 2; mt++)
#pragma unroll
            for (int nt = 0; nt < 8; nt++) {
                const int r0 = wm + mt * 16 + g;
                const int cc = wn + nt * 8 + 2 * tg;
                *reinterpret_cast<float2*>(&fsm[r0 * 132 + cc]) =
                    make_float2(acc[mt][nt][0], acc[mt][nt][1]);
                *reinterpret_cast<float2*>(&fsm[(r0 + 8) * 132 + cc]) =
                    make_float2(acc[mt][nt][2], acc[mt][nt][3]);
            }
    }
    __syncthreads();

    const int region = (MODE == M_QKV) ? (n0 / E_DIM) : 0;   // 0=Q,1=K,2=V

    if (MODE == M_QKV && region == 2) {
        // V: transposed scatter vt[h][r*64+d][j] (+ bias) fp16, coalesced along j
#pragma unroll 8
        for (int i = 0; i < 64; i++) {
            const int f = t + i * 256;
            const int m = f & 127;          // tile row -> (r, j)
            const int n = f >> 7;           // tile col
            const int nl = n0 + n - 2 * E_DIM;
            float v = fsm[m * 132 + n] + bias3[nl];
            const int h = nl >> 6, d = nl & 63;
            const int mg = m0 + m;
            const int r = mg >> 8, j = mg & 255;
            u16 hh, ll;
            splitH1(v, hh, ll);
            const size_t oi = ((size_t)h * PHEAD + r * 64 + d) * C_DIM + j;
            outH3[oi] = hh; outL3[oi] = ll;
        }
    } else {
#pragma unroll
        for (int i = 0; i < 16; i++) {
            const int f = t + i * 256;
            const int row = f >> 5;
            const int q   = f & 31;
            float4 v = *reinterpret_cast<const float4*>(&fsm[row * 132 + q * 4]);
            const int m = m0 + row;
            const int n = n0 + q * 4;
            if (MODE == M_SCORES) {
                *reinterpret_cast<float4*>(&outF[(size_t)m * C_DIM + n]) = v;
            } else if (MODE == M_PLAIN) {
                float4 bb = *reinterpret_cast<const float4*>(&bias[n]);
                v.x += bb.x; v.y += bb.y; v.z += bb.z; v.w += bb.w;
                *reinterpret_cast<float4*>(&outF[(size_t)m * E_DIM + n]) = v;
            } else if (MODE == M_QKV) {       // region 0 (Q) or 1 (K)
                const int nl = n - region * E_DIM;
                const float* bb_p = (region == 0) ? bias : bias2;
                float4 bb = *reinterpret_cast<const float4*>(&bb_p[nl]);
                v.x += bb.x; v.y += bb.y; v.z += bb.z; v.w += bb.w;
                uint32_t h01, l01, h23, l23;
                splitH2(v.x, v.y, h01, l01);
                splitH2(v.z, v.w, h23, l23);
                const int h = nl >> 6, d = nl & 63;
                const int r = m >> 8, ij = m & 255;
                const size_t oi = ((size_t)h * C_DIM + ij) * PHEAD + r * 64 + d;
                u16* dH = (region == 0) ? outH : outH2;
                u16* dL = (region == 0) ? outL : outL2;
                *reinterpret_cast<uint2*>(&dH[oi]) = make_uint2(h01, h23);
                *reinterpret_cast<uint2*>(&dL[oi]) = make_uint2(l01, l23);
            } else { // M_AV -> cb fp16 [(r*C+i)][hz*64+d]
                uint32_t h01, l01, h23, l23;
                splitH2(v.x, v.y, h01, l01);
                splitH2(v.z, v.w, h23, l23);
                const int r = n >> 6, d = n & 63;
                const size_t oi = ((size_t)r * C_DIM + m) * E_DIM + hz * 64 + d;
                *reinterpret_cast<uint2*>(&outH[oi]) = make_uint2(h01, h23);
                *reinterpret_cast<uint2*>(&outL[oi]) = make_uint2(l01, l23);
            }
        }
    }
}

// ---------------- softmax: reduce partials, scale, softmax, emit fp32 + fp16 ----------------
__global__ __launch_bounds__(256)
void softmax_kernel(const float* __restrict__ part, float* __restrict__ probs,
                    float* __restrict__ probs_out,
                    u16* __restrict__ pbh, u16* __restrict__ pbl, float alpha)
{
    const int row = blockIdx.x;
    const int h = row >> 8;
    const int i = row & 255;
    const int j = threadIdx.x;

    float v = 0.0f;
#pragma unroll
    for (int s = 0; s < SPLIT_S; s++)
        v += part[((size_t)(h * SPLIT_S + s)) * (C_DIM * C_DIM) + (size_t)i * C_DIM + j];
    v *= alpha;

    __shared__ float red[256];
    red[j] = v;
    __syncthreads();
#pragma unroll
    for (int off = 128; off > 0; off >>= 1) {
        if (j < off) red[j] = fmaxf(red[j], red[j + off]);
        __syncthreads();
    }
    const float mx = red[0];
    __syncthreads();
    const float e = expf(v - mx);
    red[j] = e;
    __syncthreads();
#pragma unroll
    for (int off = 128; off > 0; off >>= 1) {
        if (j < off) red[j] += red[j + off];
        __syncthreads();
    }
    const float p = e / red[0];

    const size_t idx = (size_t)row * C_DIM + j;
    probs[idx] = p;
    if (probs_out) probs_out[idx] = p;
    u16 hh, ll;
    splitH1(p, hh, ll);
    pbh[idx] = hh; pbl[idx] = ll;
}

// ---------------- launch ----------------
extern "C" void kernel_launch(void* const* d_in, const int* in_sizes, int n_in,
                              void* d_out, int out_size)
{
    const float* x  = (const float*)d_in[0];
    const float* Wq = (const float*)d_in[1];
    const float* bq = (const float*)d_in[2];
    const float* Wk = (const float*)d_in[3];
    const float* bk = (const float*)d_in[4];
    const float* Wv = (const float*)d_in[5];
    const float* bv = (const float*)d_in[6];
    const float* Wo = (const float*)d_in[7];
    const float* bo = (const float*)d_in[8];
    float* out = (float*)d_out;

    float* probs_out = nullptr;
    if ((size_t)out_size >= OUT_ELEMS + SCORES_ELEMS)
        probs_out = out + ((size_t)out_size - SCORES_ELEMS);

    u16 *xh, *xl, *wfh, *wfl, *woh, *wol;
    u16 *qth, *qtl, *kth, *ktl, *vth, *vtl, *pbh, *pbl, *cbh, *cbl;
    float *part, *probs;
    cudaGetSymbolAddress((void**)&xh, g_xh);   cudaGetSymbolAddress((void**)&xl, g_xl);
    cudaGetSymbolAddress((void**)&wfh, g_wfh); cudaGetSymbolAddress((void**)&wfl, g_wfl);
    cudaGetSymbolAddress((void**)&woh, g_woh); cudaGetSymbolAddress((void**)&wol, g_wol);
    cudaGetSymbolAddress((void**)&qth, g_qth); cudaGetSymbolAddress((void**)&qtl, g_qtl);
    cudaGetSymbolAddress((void**)&kth, g_kth); cudaGetSymbolAddress((void**)&ktl, g_ktl);
    cudaGetSymbolAddress((void**)&vth, g_vth); cudaGetSymbolAddress((void**)&vtl, g_vtl);
    cudaGetSymbolAddress((void**)&pbh, g_pbh); cudaGetSymbolAddress((void**)&pbl, g_pbl);
    cudaGetSymbolAddress((void**)&cbh, g_cbh); cudaGetSymbolAddress((void**)&cbl, g_cbl);
    cudaGetSymbolAddress((void**)&part, g_part);
    cudaGetSymbolAddress((void**)&probs, g_probs);

    cudaFuncSetAttribute((const void*)hm_gemm<M_QKV, 2>,    cudaFuncAttributeMaxDynamicSharedMemorySize, Cfg<2>::DYN);
    cudaFuncSetAttribute((const void*)hm_gemm<M_PLAIN, 2>,  cudaFuncAttributeMaxDynamicSharedMemorySize, Cfg<2>::DYN);
    cudaFuncSetAttribute((const void*)hm_gemm<M_AV, 2>,     cudaFuncAttributeMaxDynamicSharedMemorySize, Cfg<2>::DYN);
    cudaFuncSetAttribute((const void*)hm_gemm<M_SCORES, 3>, cudaFuncAttributeMaxDynamicSharedMemorySize, Cfg<3>::DYN);

    const float scaling = (float)(1.0 / (8.0 * sqrt(128.0)));

    // input conversions (fp16 hi/lo); weights packed into fused [Wq;Wk;Wv]
    convert_splitH<<<1024, 256>>>(x,  xh,  xl,  OUT_ELEMS / 4);
    convert_splitH<<<288,  256>>>(Wq, wfh,               wfl,               W_ELEMS / 4);
    convert_splitH<<<288,  256>>>(Wk, wfh + W_ELEMS,     wfl + W_ELEMS,     W_ELEMS / 4);
    convert_splitH<<<288,  256>>>(Wv, wfh + 2 * W_ELEMS, wfl + 2 * W_ELEMS, W_ELEMS / 4);
    convert_splitH<<<288,  256>>>(Wo, woh, wol, W_ELEMS / 4);

    dim3 blk(256);

    // fused QKV projection: N = 2304
    dim3 gqkv(3 * E_DIM / 128, MROWS / 128, 1);          // (18, 256)
    hm_gemm<M_QKV, 2><<<gqkv, blk, Cfg<2>::DYN>>>(
        xh, xl, wfh, wfl, bq, bk, bv, nullptr,
        qth, qtl, kth, ktl, vth, vtl, E_DIM, E_DIM, E_DIM);

    dim3 gsc(C_DIM / 128, C_DIM / 128, H_DIM * SPLIT_S); // (2, 2, 192)
    hm_gemm<M_SCORES, 3><<<gsc, blk, Cfg<3>::DYN>>>(
        qth, qtl, kth, ktl, nullptr, nullptr, nullptr, part,
        nullptr, nullptr, nullptr, nullptr, nullptr, nullptr,
        PHEAD / SPLIT_S, PHEAD, PHEAD);

    softmax_kernel<<<H_DIM * C_DIM, 256>>>(part, probs, probs_out, pbh, pbl, scaling);

    dim3 gav(PHEAD / 128, C_DIM / 128, H_DIM);           // (64, 2, 12)
    hm_gemm<M_AV, 2><<<gav, blk, Cfg<2>::DYN>>>(
        pbh, pbl, vth, vtl, nullptr, nullptr, nullptr, nullptr,
        cbh, cbl, nullptr, nullptr, nullptr, nullptr, C_DIM, C_DIM, C_DIM);

    dim3 gout(E_DIM / 128, MROWS / 128, 1);              // (6, 256)
    hm_gemm<M_PLAIN, 2><<<gout, blk, Cfg<2>::DYN>>>(
        cbh, cbl, woh, wol, bo, nullptr, nullptr, out,
        nullptr, nullptr, nullptr, nullptr, nullptr, nullptr, E_DIM, E_DIM, E_DIM);
}

// round 8
// speedup vs baseline: 1.8650x; 1.2217x over previous
#include <cuda_runtime.h>
#include <cuda_bf16.h>
#include <cuda_fp16.h>
#include <math.h>
#include <stdint.h>

#define R_DIM 128
#define C_DIM 256
#define E_DIM 768
#define H_DIM 12
#define DK_DIM 64
#define MROWS (R_DIM * C_DIM)            // 32768
#define PHEAD (R_DIM * DK_DIM)           // 8192
#define SPLIT_S 16
#define SCORES_ELEMS (H_DIM * C_DIM * C_DIM)   // 786432
#define OUT_ELEMS ((size_t)MROWS * E_DIM)      // 25165824
#define W_ELEMS (E_DIM * E_DIM)                // 589824

typedef unsigned short u16;

// ---------------- scratch ----------------
__device__ u16 g_xh[OUT_ELEMS],  g_xl[OUT_ELEMS];        // fp16 hi/lo
__device__ u16 g_wfh[2 * W_ELEMS], g_wfl[2 * W_ELEMS];   // fused [Wq;Wk] fp16 hi/lo
__device__ u16 g_wvh[W_ELEMS];                           // Wv fp16 hi only
__device__ u16 g_woh[W_ELEMS];                           // Wo fp16 hi only
__device__ u16 g_qth[OUT_ELEMS], g_qtl[OUT_ELEMS];       // fp16 [h][i][r*64+d] (unscaled)
__device__ u16 g_kth[OUT_ELEMS], g_ktl[OUT_ELEMS];       // fp16 [h][j][r*64+d]
__device__ u16 g_vth[OUT_ELEMS];                         // fp16 [h][r*64+d][j]
__device__ u16 g_pbh[SCORES_ELEMS];                      // fp16 probs [h][i][j]
__device__ u16 g_cbh[OUT_ELEMS];                         // fp16 [(r*C+i)][h*64+d]
__device__ float g_part[(size_t)SPLIT_S * SCORES_ELEMS];
__device__ float g_probs[SCORES_ELEMS];

// ---------------- helpers ----------------
__device__ __forceinline__ uint32_t smem_u32(const void* p) {
    uint32_t a;
    asm("{ .reg .u64 t; cvta.to.shared.u64 t, %1; cvt.u32.u64 %0, t; }" : "=r"(a) : "l"(p));
    return a;
}
__device__ __forceinline__ void splitH2(float x, float y, uint32_t& h, uint32_t& l) {
    __half2 h2 = __floats2half2_rn(x, y);
    float2 hf = __half22float2(h2);
    __half2 l2 = __floats2half2_rn(x - hf.x, y - hf.y);
    h = *reinterpret_cast<uint32_t*>(&h2);
    l = *reinterpret_cast<uint32_t*>(&l2);
}
__device__ __forceinline__ void ldm4(uint32_t r[4], uint32_t addr) {
    asm volatile("ldmatrix.sync.aligned.m8n8.x4.shared.b16 {%0,%1,%2,%3}, [%4];"
                 : "=r"(r[0]), "=r"(r[1]), "=r"(r[2]), "=r"(r[3]) : "r"(addr));
}
__device__ __forceinline__ void mma_f32(float c[4], const uint32_t a[4],
                                        uint32_t b0, uint32_t b1) {
    asm volatile("mma.sync.aligned.m16n8k16.row.col.f32.f16.f16.f32 "
        "{%0,%1,%2,%3}, {%4,%5,%6,%7}, {%8,%9}, {%0,%1,%2,%3};"
        : "+f"(c[0]), "+f"(c[1]), "+f"(c[2]), "+f"(c[3])
        : "r"(a[0]), "r"(a[1]), "r"(a[2]), "r"(a[3]), "r"(b0), "r"(b1));
}
__device__ __forceinline__ void mma_f16(uint32_t c[2], const uint32_t a[4],
                                        uint32_t b0, uint32_t b1) {
    asm volatile("mma.sync.aligned.m16n8k16.row.col.f16.f16.f16.f16 "
        "{%0,%1}, {%2,%3,%4,%5}, {%6,%7}, {%0,%1};"
        : "+r"(c[0]), "+r"(c[1])
        : "r"(a[0]), "r"(a[1]), "r"(a[2]), "r"(a[3]), "r"(b0), "r"(b1));
}
#define CP16(dst, src) \
    asm volatile("cp.async.cg.shared.global [%0], [%1], 16;" :: "r"(dst), "l"(src) : "memory")
#define CP_COMMIT() asm volatile("cp.async.commit_group;" ::: "memory")
#define CP_WAITN(n) asm volatile("cp.async.wait_group %0;" :: "n"(n) : "memory")

// ---------------- converts ----------------
__global__ __launch_bounds__(256)
void convert_splitH(const float* __restrict__ src, u16* __restrict__ h,
                    u16* __restrict__ l, int n4)
{
    for (int i = blockIdx.x * blockDim.x + threadIdx.x; i < n4; i += gridDim.x * blockDim.x) {
        float4 v = reinterpret_cast<const float4*>(src)[i];
        uint32_t h01, l01, h23, l23;
        splitH2(v.x, v.y, h01, l01);
        splitH2(v.z, v.w, h23, l23);
        reinterpret_cast<uint2*>(h)[i] = make_uint2(h01, h23);
        reinterpret_cast<uint2*>(l)[i] = make_uint2(l01, l23);
    }
}
__global__ __launch_bounds__(256)
void convert_hi(const float* __restrict__ src, u16* __restrict__ h, int n4)
{
    for (int i = blockIdx.x * blockDim.x + threadIdx.x; i < n4; i += gridDim.x * blockDim.x) {
        float4 v = reinterpret_cast<const float4*>(src)[i];
        __half2 a = __floats2half2_rn(v.x, v.y);
        __half2 b = __floats2half2_rn(v.z, v.w);
        reinterpret_cast<uint2*>(h)[i] =
            make_uint2(*reinterpret_cast<uint32_t*>(&a), *reinterpret_cast<uint32_t*>(&b));
    }
}

// ---------------- HMMA GEMM: C = A(MxK) * B(NxK)^T ----------------
// NPASS=1: AhBh only.  NPASS=2: + AlBh (f16 acc).  NPASS=3: + AhBl (f16 acc).
enum { M_PLAIN = 0, M_QK = 1, M_V = 2, M_SCORES = 3, M_AV = 4 };

template<int NPASS> struct Cfg;
template<> struct Cfg<1> { static const int STAGE = 20480, NST = 4, DYN = 81920; };
template<> struct Cfg<2> { static const int STAGE = 30720, NST = 3, DYN = 92160; };
template<> struct Cfg<3> { static const int STAGE = 40960, NST = 2, DYN = 81920; };

template<int MODE, int NPASS>
__global__ __launch_bounds__(256, 2)
void hm_gemm(const u16* __restrict__ Ah, const u16* __restrict__ Al,
             const u16* __restrict__ Bh, const u16* __restrict__ Bl,
             const float* __restrict__ bias, const float* __restrict__ bias2,
             float* __restrict__ outF,
             u16* __restrict__ outH,  u16* __restrict__ outL,
             u16* __restrict__ outH2, u16* __restrict__ outL2,
             int K, int lda, int ldb)
{
    extern __shared__ char dynsmem[];
    const int t    = threadIdx.x;
    const int lane = t & 31;
    const int wid  = t >> 5;
    const int wm   = (wid & 3) * 32;
    const int wn   = (wid >> 2) * 64;
    const int m0   = blockIdx.y * 128;
    const int n0   = blockIdx.x * 128;
    const int STAGE = Cfg<NPASS>::STAGE;
    const int NST   = Cfg<NPASS>::NST;
    const uint32_t BH_OFF = (NPASS == 1) ? 10240u : 20480u;

    int hz = 0;
    if (MODE == M_SCORES) {
        const int z = blockIdx.z;
        const int h = z >> 4, s = z & 15;
        const size_t off = (size_t)h * C_DIM * PHEAD + (size_t)s * (PHEAD / SPLIT_S);
        Ah += off; Al += off; Bh += off; Bl += off;
        outF += (size_t)z * (C_DIM * C_DIM);
    } else if (MODE == M_AV) {
        hz = blockIdx.z;
        Ah += (size_t)hz * C_DIM * C_DIM;
        Bh += (size_t)hz * PHEAD * C_DIM;
    }

    const uint32_t smb = smem_u32(dynsmem);
    const int NC = K >> 5;

    auto issue = [&](int c, int s) {
        const int kk = c << 5;
        const uint32_t sb = smb + s * STAGE;
#pragma unroll
        for (int it = 0; it < 2; it++) {
            const int f   = t + it * 256;      // 0..511
            const int row = f >> 2;            // 0..127
            const int k8  = f & 3;
            const uint32_t so = (uint32_t)(row * 80 + k8 * 16);
            const size_t ga = (size_t)(m0 + row) * lda + kk + k8 * 8;
            const size_t gb = (size_t)(n0 + row) * ldb + kk + k8 * 8;
            CP16(sb + so, Ah + ga);
            if (NPASS >= 2) CP16(sb + 10240 + so, Al + ga);
            CP16(sb + BH_OFF + so, Bh + gb);
            if (NPASS == 3) CP16(sb + 30720 + so, Bl + gb);
        }
        CP_COMMIT();
    };

    float    acc[2][8][4];
    uint32_t a16[2][8][2];
#pragma unroll
    for (int mt = 0; mt < 2; mt++)
#pragma unroll
        for (int nt = 0; nt < 8; nt++) {
#pragma unroll
            for (int e = 0; e < 4; e++) acc[mt][nt][e] = 0.0f;
            a16[mt][nt][0] = 0u; a16[mt][nt][1] = 0u;
        }

    const uint32_t ro = (uint32_t)(((lane >> 3) & 1) * 8 + (lane & 7));
    const uint32_t co = (lane & 16) ? 16u : 0u;
    const uint32_t aoff = (uint32_t)(wm + ro) * 80 + co;
    const uint32_t boff = (uint32_t)(wn + ro) * 80 + co;

    // prologue: NST-1 chunks
    issue(0, 0);
    if (NST >= 3 && NC > 1) issue(1, 1);
    if (NST >= 4 && NC > 2) issue(2, 2);

    for (int c = 0; c < NC; c++) {
        if (NST == 4) {
            if (c + 1 >= NC)      { CP_WAITN(0); }
            else if (c + 2 >= NC) { CP_WAITN(1); }
            else                  { CP_WAITN(2); }
        } else if (NST == 3) {
            if (c + 1 >= NC) { CP_WAITN(0); } else { CP_WAITN(1); }
        } else {
            CP_WAITN(0);
        }
        __syncthreads();
        if (c + NST - 1 < NC) issue(c + NST - 1, (c + NST - 1) % NST);

        const uint32_t sb = smb + (c % NST) * STAGE;
#pragma unroll
        for (int kh = 0; kh < 2; kh++) {
            const uint32_t kB = kh * 32;
            uint32_t aH[2][4], bH[4][4];
            ldm4(aH[0], sb + aoff + kB);
            ldm4(aH[1], sb + aoff + 16 * 80 + kB);
#pragma unroll
            for (int np = 0; np < 4; np++)
                ldm4(bH[np], sb + BH_OFF + boff + np * 16 * 80 + kB);
            // pass 1: Ah*Bh -> f32 acc
#pragma unroll
            for (int mt = 0; mt < 2; mt++)
#pragma unroll
                for (int np = 0; np < 4; np++) {
                    mma_f32(acc[mt][np * 2 + 0], aH[mt], bH[np][0], bH[np][2]);
                    mma_f32(acc[mt][np * 2 + 1], aH[mt], bH[np][1], bH[np][3]);
                }
            // pass 2: Al*Bh -> f16 acc
            if (NPASS >= 2) {
                uint32_t aL[2][4];
                ldm4(aL[0], sb + 10240 + aoff + kB);
                ldm4(aL[1], sb + 10240 + aoff + 16 * 80 + kB);
#pragma unroll
                for (int mt = 0; mt < 2; mt++)
#pragma unroll
                    for (int np = 0; np < 4; np++) {
                        mma_f16(a16[mt][np * 2 + 0], aL[mt], bH[np][0], bH[np][2]);
                        mma_f16(a16[mt][np * 2 + 1], aL[mt], bH[np][1], bH[np][3]);
                    }
            }
            // pass 3: Ah*Bl -> f16 acc
            if (NPASS == 3) {
#pragma unroll
                for (int np = 0; np < 4; np++) {
                    uint32_t bL[4];
                    ldm4(bL, sb + 30720 + boff + np * 16 * 80 + kB);
                    mma_f16(a16[0][np * 2 + 0], aH[0], bL[0], bL[2]);
                    mma_f16(a16[0][np * 2 + 1], aH[0], bL[1], bL[3]);
                    mma_f16(a16[1][np * 2 + 0], aH[1], bL[0], bL[2]);
                    mma_f16(a16[1][np * 2 + 1], aH[1], bL[1], bL[3]);
                }
            }
        }
    }
    __syncthreads();   // protect smem reuse by the epilogue

    // fold f16 acc into f32 acc
    if (NPASS >= 2) {
#pragma unroll
        for (int mt = 0; mt < 2; mt++)
#pragma unroll
            for (int nt = 0; nt < 8; nt++) {
                float2 p0 = __half22float2(*reinterpret_cast<__half2*>(&a16[mt][nt][0]));
                float2 p1 = __half22float2(*reinterpret_cast<__half2*>(&a16[mt][nt][1]));
                acc[mt][nt][0] += p0.x; acc[mt][nt][1] += p0.y;
                acc[mt][nt][2] += p1.x; acc[mt][nt][3] += p1.y;
            }
    }

    // -------- epilogue: acc -> smem fp32 staging (128x132) -> global --------
    float* fsm = reinterpret_cast<float*>(dynsmem);
    {
        const int g  = lane >> 2;
        const int tg = lane & 3;
#pragma unroll
        for (int mt = 0; mt < 2; mt++)
#pragma unroll
            for (int nt = 0; nt < 8; nt++) {
                const int r0 = wm + mt * 16 + g;
                const int cc = wn + nt * 8 + 2 * tg;
                *reinterpret_cast<float2*>(&fsm[r0 * 132 + cc]) =
                    make_float2(acc[mt][nt][0], acc[mt][nt][1]);
                *reinterpret_cast<float2*>(&fsm[(r0 + 8) * 132 + cc]) =
                    make_float2(acc[mt][nt][2], acc[mt][nt][3]);
            }
    }
    __syncthreads();

    if (MODE == M_V) {
        // V: transposed scatter vt[h][r*64+d][j] (+ bias) fp16 hi only
#pragma unroll 8
        for (int i = 0; i < 64; i++) {
            const int f = t + i * 256;
            const int m = f & 127;          // tile row -> (r, j)
            const int n = f >> 7;           // tile col -> (h, d)
            const int ng = n0 + n;
            float v = fsm[m * 132 + n] + bias[ng];
            const int h = ng >> 6, d = ng & 63;
            const int mg = m0 + m;
            const int r = mg >> 8, j = mg & 255;
            __half hh = __float2half_rn(v);
            outH[((size_t)h * PHEAD + r * 64 + d) * C_DIM + j] = *reinterpret_cast<u16*>(&hh);
        }
    } else {
#pragma unroll
        for (int i = 0; i < 16; i++) {
            const int f = t + i * 256;
            const int row = f >> 5;
            const int q   = f & 31;
            float4 v = *reinterpret_cast<const float4*>(&fsm[row * 132 + q * 4]);
            const int m = m0 + row;
            const int n = n0 + q * 4;
            if (MODE == M_SCORES) {
                *reinterpret_cast<float4*>(&outF[(size_t)m * C_DIM + n]) = v;
            } else if (MODE == M_PLAIN) {
                float4 bb = *reinterpret_cast<const float4*>(&bias[n]);
                v.x += bb.x; v.y += bb.y; v.z += bb.z; v.w += bb.w;
                *reinterpret_cast<float4*>(&outF[(size_t)m * E_DIM + n]) = v;
            } else if (MODE == M_QK) {       // region 0 (Q) or 1 (K)
                const int region = (n >= E_DIM) ? 1 : 0;
                const int nl = n - region * E_DIM;
                const float* bb_p = region ? bias2 : bias;
                float4 bb = *reinterpret_cast<const float4*>(&bb_p[nl]);
                v.x += bb.x; v.y += bb.y; v.z += bb.z; v.w += bb.w;
                uint32_t h01, l01, h23, l23;
                splitH2(v.x, v.y, h01, l01);
                splitH2(v.z, v.w, h23, l23);
                const int h = nl >> 6, d = nl & 63;
                const int r = m >> 8, ij = m & 255;
                const size_t oi = ((size_t)h * C_DIM + ij) * PHEAD + r * 64 + d;
                u16* dH = region ? outH2 : outH;
                u16* dL = region ? outL2 : outL;
                *reinterpret_cast<uint2*>(&dH[oi]) = make_uint2(h01, h23);
                *reinterpret_cast<uint2*>(&dL[oi]) = make_uint2(l01, l23);
            } else { // M_AV -> cb fp16 hi [(r*C+i)][hz*64+d]
                __half2 a = __floats2half2_rn(v.x, v.y);
                __half2 b = __floats2half2_rn(v.z, v.w);
                const int r = n >> 6, d = n & 63;
                const size_t oi = ((size_t)r * C_DIM + m) * E_DIM + hz * 64 + d;
                *reinterpret_cast<uint2*>(&outH[oi]) =
                    make_uint2(*reinterpret_cast<uint32_t*>(&a), *reinterpret_cast<uint32_t*>(&b));
            }
        }
    }
}

// ---------------- softmax: reduce partials, scale, softmax, emit fp32 + fp16 ----------------
__global__ __launch_bounds__(256)
void softmax_kernel(const float* __restrict__ part, float* __restrict__ probs,
                    float* __restrict__ probs_out, u16* __restrict__ pbh, float alpha)
{
    const int row = blockIdx.x;
    const int h = row >> 8;
    const int i = row & 255;
    const int j = threadIdx.x;

    float v = 0.0f;
#pragma unroll
    for (int s = 0; s < SPLIT_S; s++)
        v += part[((size_t)(h * SPLIT_S + s)) * (C_DIM * C_DIM) + (size_t)i * C_DIM + j];
    v *= alpha;

    __shared__ float red[256];
    red[j] = v;
    __syncthreads();
#pragma unroll
    for (int off = 128; off > 0; off >>= 1) {
        if (j < off) red[j] = fmaxf(red[j], red[j + off]);
        __syncthreads();
    }
    const float mx = red[0];
    __syncthreads();
    const float e = expf(v - mx);
    red[j] = e;
    __syncthreads();
#pragma unroll
    for (int off = 128; off > 0; off >>= 1) {
        if (j < off) red[j] += red[j + off];
        __syncthreads();
    }
    const float p = e / red[0];

    const size_t idx = (size_t)row * C_DIM + j;
    probs[idx] = p;
    if (probs_out) probs_out[idx] = p;
    __half hh = __float2half_rn(p);
    pbh[idx] = *reinterpret_cast<u16*>(&hh);
}

// ---------------- launch ----------------
extern "C" void kernel_launch(void* const* d_in, const int* in_sizes, int n_in,
                              void* d_out, int out_size)
{
    const float* x  = (const float*)d_in[0];
    const float* Wq = (const float*)d_in[1];
    const float* bq = (const float*)d_in[2];
    const float* Wk = (const float*)d_in[3];
    const float* bk = (const float*)d_in[4];
    const float* Wv = (const float*)d_in[5];
    const float* bv = (const float*)d_in[6];
    const float* Wo = (const float*)d_in[7];
    const float* bo = (const float*)d_in[8];
    float* out = (float*)d_out;

    float* probs_out = nullptr;
    if ((size_t)out_size >= OUT_ELEMS + SCORES_ELEMS)
        probs_out = out + ((size_t)out_size - SCORES_ELEMS);

    u16 *xh, *xl, *wfh, *wfl, *wvh, *woh;
    u16 *qth, *qtl, *kth, *ktl, *vth, *pbh, *cbh;
    float *part, *probs;
    cudaGetSymbolAddress((void**)&xh, g_xh);   cudaGetSymbolAddress((void**)&xl, g_xl);
    cudaGetSymbolAddress((void**)&wfh, g_wfh); cudaGetSymbolAddress((void**)&wfl, g_wfl);
    cudaGetSymbolAddress((void**)&wvh, g_wvh); cudaGetSymbolAddress((void**)&woh, g_woh);
    cudaGetSymbolAddress((void**)&qth, g_qth); cudaGetSymbolAddress((void**)&qtl, g_qtl);
    cudaGetSymbolAddress((void**)&kth, g_kth); cudaGetSymbolAddress((void**)&ktl, g_ktl);
    cudaGetSymbolAddress((void**)&vth, g_vth);
    cudaGetSymbolAddress((void**)&pbh, g_pbh);
    cudaGetSymbolAddress((void**)&cbh, g_cbh);
    cudaGetSymbolAddress((void**)&part, g_part);
    cudaGetSymbolAddress((void**)&probs, g_probs);

    cudaFuncSetAttribute((const void*)hm_gemm<M_QK, 2>,     cudaFuncAttributeMaxDynamicSharedMemorySize, Cfg<2>::DYN);
    cudaFuncSetAttribute((const void*)hm_gemm<M_V, 1>,      cudaFuncAttributeMaxDynamicSharedMemorySize, Cfg<1>::DYN);
    cudaFuncSetAttribute((const void*)hm_gemm<M_SCORES, 3>, cudaFuncAttributeMaxDynamicSharedMemorySize, Cfg<3>::DYN);
    cudaFuncSetAttribute((const void*)hm_gemm<M_AV, 1>,     cudaFuncAttributeMaxDynamicSharedMemorySize, Cfg<1>::DYN);
    cudaFuncSetAttribute((const void*)hm_gemm<M_PLAIN, 1>,  cudaFuncAttributeMaxDynamicSharedMemorySize, Cfg<1>::DYN);

    const float scaling = (float)(1.0 / (8.0 * sqrt(128.0)));

    convert_splitH<<<1024, 256>>>(x,  xh,  xl,  OUT_ELEMS / 4);
    convert_splitH<<<288,  256>>>(Wq, wfh,           wfl,           W_ELEMS / 4);
    convert_splitH<<<288,  256>>>(Wk, wfh + W_ELEMS, wfl + W_ELEMS, W_ELEMS / 4);
    convert_hi<<<288, 256>>>(Wv, wvh, W_ELEMS / 4);
    convert_hi<<<288, 256>>>(Wo, woh, W_ELEMS / 4);

    dim3 blk(256);

    // fused QK projection: N = 1536, 2-pass
    dim3 gqk(2 * E_DIM / 128, MROWS / 128, 1);           // (12, 256)
    hm_gemm<M_QK, 2><<<gqk, blk, Cfg<2>::DYN>>>(
        xh, xl, wfh, wfl, bq, bk, nullptr,
        qth, qtl, kth, ktl, E_DIM, E_DIM, E_DIM);

    // V projection: 1-pass
    dim3 gv(E_DIM / 128, MROWS / 128, 1);                // (6, 256)
    hm_gemm<M_V, 1><<<gv, blk, Cfg<1>::DYN>>>(
        xh, nullptr, wvh, nullptr, bv, nullptr, nullptr,
        vth, nullptr, nullptr, nullptr, E_DIM, E_DIM, E_DIM);

    // scores: 3-pass (protect probs)
    dim3 gsc(C_DIM / 128, C_DIM / 128, H_DIM * SPLIT_S); // (2, 2, 192)
    hm_gemm<M_SCORES, 3><<<gsc, blk, Cfg<3>::DYN>>>(
        qth, qtl, kth, ktl, nullptr, nullptr, part,
        nullptr, nullptr, nullptr, nullptr, PHEAD / SPLIT_S, PHEAD, PHEAD);

    softmax_kernel<<<H_DIM * C_DIM, 256>>>(part, probs, probs_out, pbh, scaling);

    // AV: 1-pass
    dim3 gav(PHEAD / 128, C_DIM / 128, H_DIM);           // (64, 2, 12)
    hm_gemm<M_AV, 1><<<gav, blk, Cfg<1>::DYN>>>(
        pbh, nullptr, vth, nullptr, nullptr, nullptr, nullptr,
        cbh, nullptr, nullptr, nullptr, C_DIM, C_DIM, C_DIM);

    // O projection: 1-pass
    dim3 gout(E_DIM / 128, MROWS / 128, 1);              // (6, 256)
    hm_gemm<M_PLAIN, 1><<<gout, blk, Cfg<1>::DYN>>>(
        cbh, nullptr, woh, nullptr, bo, nullptr, out,
        nullptr, nullptr, nullptr, nullptr, E_DIM, E_DIM, E_DIM);
}